// round 9
// baseline (speedup 1.0000x reference)
#include <cuda_runtime.h>
#include <cuda_fp16.h>
#include <math.h>
#include <stdint.h>

#define DD 512
#define NN 128
#define BB 2
#define MBIG (BB*NN*NN)     // 32768 rows for big GEMMs
#define XROWS (BB*NN)       // 256 rows for small GEMMs

// ---------------- scratch (static device allocations; no cudaMalloc) ----------------
__device__ __half g_AH[MBIG*DD];            // rel plane A (fp16)
__device__ __half g_BH[MBIG*DD];            // rel plane B (fp16)
__device__ __half g_WgH[DD*DD];             // Wg3^T  fp16 [n][k]
__device__ __half g_WeH[DD*DD];             // Wesa^T fp16 [n][k]
__device__ float g_u [XROWS*DD];
__device__ float g_v [XROWS*DD];
__device__ float g_s [XROWS*DD];
__device__ float g_t [XROWS*DD];
__device__ float g_p [XROWS*DD];
__device__ float g_q [XROWS*DD];
__device__ float g_x1[XROWS*DD];
__device__ float g_x2[XROWS*DD];
__device__ float g_c [DD];
__device__ float g_mx [XROWS*DD];
__device__ float g_inv[XROWS*DD];

// ---------------- helpers ----------------
__device__ __forceinline__ uint32_t smem_u32(const void* p) {
    uint32_t a;
    asm("{ .reg .u64 t; cvta.to.shared.u64 t, %1; cvt.u32.u64 %0, t; }" : "=r"(a) : "l"(p));
    return a;
}
__device__ __forceinline__ void mma16816(float* c, const uint32_t* a, const uint32_t* b) {
    asm volatile(
        "mma.sync.aligned.m16n8k16.row.col.f32.f16.f16.f32 "
        "{%0,%1,%2,%3},{%4,%5,%6,%7},{%8,%9},{%0,%1,%2,%3};"
        : "+f"(c[0]), "+f"(c[1]), "+f"(c[2]), "+f"(c[3])
        : "r"(a[0]), "r"(a[1]), "r"(a[2]), "r"(a[3]), "r"(b[0]), "r"(b[1]));
}
#define LDSM4(r0,r1,r2,r3,addr) \
    asm volatile("ldmatrix.sync.aligned.m8n8.x4.shared.b16 {%0,%1,%2,%3}, [%4];" \
        : "=r"(r0),"=r"(r1),"=r"(r2),"=r"(r3) : "r"(addr))
__device__ __forceinline__ void cp16(uint32_t dst, const void* src) {
    asm volatile("cp.async.cg.shared.global [%0], [%1], 16;" :: "r"(dst), "l"(src) : "memory");
}
// fast tanh: abs err ~1e-7, saturates correctly at +/-inf
__device__ __forceinline__ float ftanh(float x) {
    float e = __expf(2.0f * x);
    return 1.0f - __fdividef(2.0f, e + 1.0f);
}

// ---------------- weight transpose+f16: out[n][k] = f16(W[k][n]) ----------------
__global__ void transsplit_kernel(const float* __restrict__ W, __half* __restrict__ Wh) {
    __shared__ float tile[32][33];
    int x = blockIdx.x * 32 + threadIdx.x;
    int y = blockIdx.y * 32 + threadIdx.y;
    #pragma unroll
    for (int r = 0; r < 32; r += 8) tile[threadIdx.y + r][threadIdx.x] = W[(y + r) * DD + x];
    __syncthreads();
    x = blockIdx.y * 32 + threadIdx.x;   // now k index
    y = blockIdx.x * 32 + threadIdx.y;   // now n index
    #pragma unroll
    for (int r = 0; r < 32; r += 8)
        Wh[(y + r) * DD + x] = __float2half_rn(tile[threadIdx.x][threadIdx.y + r]);
}

// ---------------- c = b_rel @ Wg3 + b_gr ----------------
__global__ void cvec_kernel(const float* __restrict__ b_rel,
                            const float* __restrict__ Wg3,
                            const float* __restrict__ b_gr,
                            float* __restrict__ c) {
    int d = threadIdx.x;
    float acc = b_gr[d];
    #pragma unroll 8
    for (int k = 0; k < DD; ++k)
        acc += b_rel[k] * Wg3[k*DD + d];
    c[d] = acc;
}

// ---------------- batched small GEMM: C = act(A@W [+bias] [+Cadd]) ----------------
// tile 32(M) x 64(N), 256 threads, 2x4 microtile -> 64 CTAs/job for M=256
struct SJob {
    const float* A; const float* W; const float* bias; const float* Cadd;
    float* C; int act; int pad;
};
struct SBatch { SJob jobs[5]; };

__global__ __launch_bounds__(256)
void sgemm_batch_kernel(SBatch batch) {
    SJob jb = batch.jobs[blockIdx.z];
    __shared__ float As[32][36];   // [k][m], pad 4
    __shared__ float Bs[32][64];   // [k][n]
    int t  = threadIdx.x;
    int tx = t & 15, ty = t >> 4;
    int n0 = blockIdx.x << 6, m0 = blockIdx.y << 5;
    int arow = t >> 3, aseg = (t & 7) << 2;   // 32 m-rows, 4 k-floats each
    int bk = t >> 3, bn = (t & 7) << 3;       // 32 k-rows, 8 n-floats each
    const float* Aptr = jb.A + (m0 + arow) * DD + aseg;
    const float* Bptr = jb.W + bk * DD + n0 + bn;

    float acc[2][4] = {};
    for (int kt = 0; kt < DD/32; ++kt) {
        float4 av  = *(const float4*)(Aptr + kt*32);
        float4 bv0 = *(const float4*)(Bptr + kt*32*DD);
        float4 bv1 = *(const float4*)(Bptr + kt*32*DD + 4);
        __syncthreads();
        As[aseg+0][arow]=av.x; As[aseg+1][arow]=av.y;
        As[aseg+2][arow]=av.z; As[aseg+3][arow]=av.w;
        *(float4*)&Bs[bk][bn]   = bv0;
        *(float4*)&Bs[bk][bn+4] = bv1;
        __syncthreads();
        #pragma unroll
        for (int kk = 0; kk < 32; ++kk) {
            float a0 = As[kk][ty*2], a1 = As[kk][ty*2+1];
            float4 b = *(const float4*)&Bs[kk][tx<<2];
            acc[0][0]+=a0*b.x; acc[0][1]+=a0*b.y; acc[0][2]+=a0*b.z; acc[0][3]+=a0*b.w;
            acc[1][0]+=a1*b.x; acc[1][1]+=a1*b.y; acc[1][2]+=a1*b.z; acc[1][3]+=a1*b.w;
        }
    }
    int n = n0 + (tx<<2);
    float4 bb = make_float4(0.f, 0.f, 0.f, 0.f);
    if (jb.bias) bb = *(const float4*)(jb.bias + n);
    #pragma unroll
    for (int mm = 0; mm < 2; ++mm) {
        int m = m0 + ty*2 + mm;
        float4 r = make_float4(acc[mm][0]+bb.x, acc[mm][1]+bb.y,
                               acc[mm][2]+bb.z, acc[mm][3]+bb.w);
        if (jb.Cadd) {
            float4 cv = *(const float4*)(jb.Cadd + m*DD + n);
            r.x += cv.x; r.y += cv.y; r.z += cv.z; r.w += cv.w;
        }
        if (jb.act) { r.x=ftanh(r.x); r.y=ftanh(r.y); r.z=ftanh(r.z); r.w=ftanh(r.w); }
        *(float4*)&jb.C[m*DD + n] = r;
    }
}

// ---------------- rel1 init: f16(tanh(s_i + t_j + c)) ----------------
__global__ __launch_bounds__(256)
void init_rel_kernel(const float* __restrict__ s, const float* __restrict__ t,
                     const float* __restrict__ c, __half* __restrict__ RH) {
    __shared__ float srow[DD];
    int bi = blockIdx.x;                 // b*128 + i
    int b  = bi >> 7;
    int tid = threadIdx.x;
    #pragma unroll
    for (int d = tid; d < DD; d += 256) srow[d] = s[bi * DD + d] + c[d];
    __syncthreads();
    int j0 = blockIdx.y * 32;
    int d = tid * 2;
    for (int j = j0; j < j0 + 32; ++j) {
        const float* trow = t + (size_t)((b << 7) + j) * DD;
        float v0 = ftanh(srow[d]   + trow[d]);
        float v1 = ftanh(srow[d+1] + trow[d+1]);
        size_t m = (size_t)bi * NN + j;
        *(__half2*)&RH[m * DD + d] = __halves2half2(__float2half_rn(v0), __float2half_rn(v1));
    }
}

// ================= big GEMM via mma.sync (pure fp16 operands, fp32 accum) =================
// C[32768,512] = A @ Wt^T. Per-CTA tile 128x128, K chunks of 32.
// SMEM per buffer (row stride 80B = 64 data + 16 pad): A +0, B +10240; buffer 20480, x2.
// MODE 0: v = tanh(D + P[b,i,:] + Q[b,j,:] + bias) -> Chi (fp16)
// MODE 1: v = D + bias -> Chi (fp16)
#define HG_SMEM (2*20480)

template<int MODE>
__global__ __launch_bounds__(256, 2)
void hgemm_kernel(const __half* __restrict__ Ah, const __half* __restrict__ Bh,
                  const float* __restrict__ P, const float* __restrict__ Q,
                  const float* __restrict__ bias, __half* __restrict__ Chi) {
    extern __shared__ __align__(16) char sm[];
    const uint32_t smBase = smem_u32(sm);
    const int tid = threadIdx.x;
    const int n0 = blockIdx.x << 7, m0 = blockIdx.y << 7;

    // --- cp.async: 2 groups of 128 threads; each thread one row (64 B = 4 x 16B) ---
    const int mat = tid >> 7, tt = tid & 127;
    const __half* plane = mat ? (Bh + (size_t)(n0 + tt) * DD) : (Ah + (size_t)(m0 + tt) * DD);
    const uint32_t dstoff = (uint32_t)mat * 10240u + (uint32_t)tt * 80u;

    const int lane = tid & 31, wid = tid >> 5;
    const int g = lane >> 2, q = lane & 3;
    const int wm = (wid & 1) * 64, wn = (wid >> 1) * 32;

    // ldmatrix lane addressing
    const int lr = lane & 7, sub = lane >> 3;
    const uint32_t rowsel = (uint32_t)((sub & 1) * 8 + lr);
    const uint32_t colsel = (uint32_t)((sub >> 1) * 16);
    const uint32_t aoff = (uint32_t)(wm + rowsel) * 80u + colsel;            // + mt*1280 + ks*32
    const uint32_t boff = 10240u + (uint32_t)(wn + rowsel) * 80u + colsel;   // + ntp*1280 + ks*32

    float cacc[4][4][4];
    #pragma unroll
    for (int a = 0; a < 4; ++a)
        #pragma unroll
        for (int b = 0; b < 4; ++b)
            #pragma unroll
            for (int e = 0; e < 4; ++e) cacc[a][b][e] = 0.f;

    // preload chunk 0
    {
        uint32_t d = smBase + dstoff;
        #pragma unroll
        for (int sg = 0; sg < 4; ++sg) cp16(d + sg*16, plane + sg*8);
        asm volatile("cp.async.commit_group;" ::: "memory");
    }

    for (int kc = 0; kc < 16; ++kc) {
        if (kc < 15) {
            uint32_t d = smBase + (uint32_t)(((kc + 1) & 1)) * 20480u + dstoff;
            const __half* sp = plane + (kc + 1) * 32;
            #pragma unroll
            for (int sg = 0; sg < 4; ++sg) cp16(d + sg*16, sp + sg*8);
            asm volatile("cp.async.commit_group;" ::: "memory");
            asm volatile("cp.async.wait_group 1;" ::: "memory");
        } else {
            asm volatile("cp.async.wait_group 0;" ::: "memory");
        }
        __syncthreads();

        uint32_t bufb = smBase + (uint32_t)(kc & 1) * 20480u;
        #pragma unroll
        for (int ks = 0; ks < 2; ++ks) {
            uint32_t kso = (uint32_t)(ks * 32);
            uint32_t bfh[4][2];
            #pragma unroll
            for (int ntp = 0; ntp < 2; ++ntp) {
                uint32_t ba = bufb + boff + (uint32_t)ntp * 1280u + kso;
                uint32_t r0, r1, r2, r3;
                LDSM4(r0, r1, r2, r3, ba);
                bfh[2*ntp][0]=r0; bfh[2*ntp+1][0]=r1; bfh[2*ntp][1]=r2; bfh[2*ntp+1][1]=r3;
            }
            #pragma unroll
            for (int mt = 0; mt < 4; ++mt) {
                uint32_t aa = bufb + aoff + (uint32_t)mt * 1280u + kso;
                uint32_t ah[4];
                LDSM4(ah[0], ah[1], ah[2], ah[3], aa);
                #pragma unroll
                for (int nt = 0; nt < 4; ++nt)
                    mma16816(cacc[mt][nt], ah, bfh[nt]);
            }
        }
        __syncthreads();
    }

    // ---- epilogue ----
    #pragma unroll
    for (int mt = 0; mt < 4; ++mt) {
        #pragma unroll
        for (int nt = 0; nt < 4; ++nt) {
            int col = n0 + wn + nt*8 + q*2;
            float b0 = bias[col], b1 = bias[col + 1];
            #pragma unroll
            for (int rh = 0; rh < 2; ++rh) {
                int r = m0 + wm + mt*16 + g + rh*8;
                float v0 = cacc[mt][nt][rh*2 + 0] + b0;
                float v1 = cacc[mt][nt][rh*2 + 1] + b1;
                if (MODE == 0) {
                    int b = r >> 14, ii = (r >> 7) & 127, jj = r & 127;
                    const float* pr = P + (size_t)(((b<<7)+ii)) * DD;
                    const float* qr = Q + (size_t)(((b<<7)+jj)) * DD;
                    v0 = ftanh(v0 + pr[col]   + qr[col]);
                    v1 = ftanh(v1 + pr[col+1] + qr[col+1]);
                }
                *(__half2*)&Chi[(size_t)r * DD + col] =
                    __halves2half2(__float2half_rn(v0), __float2half_rn(v1));
            }
        }
    }
}

// ---------------- softmax pass A: per (b,j,d) max & 1/sumexp over i (fp16 rel) ----------------
__global__ void softmax_stats_kernel(const __half* __restrict__ rel,
                                     float* __restrict__ mx, float* __restrict__ inv) {
    int bj = blockIdx.x;            // b*NN + j
    int b = bj >> 7, j = bj & 127;
    int d = threadIdx.x;
    const __half* ptr = rel + (size_t)((b << 14) + j) * DD + d;
    float m = -1e30f;
    #pragma unroll 8
    for (int i = 0; i < NN; ++i) m = fmaxf(m, __half2float(ptr[(size_t)i * NN * DD]));
    float s = 0.f;
    #pragma unroll 8
    for (int i = 0; i < NN; ++i) s += __expf(__half2float(ptr[(size_t)i * NN * DD]) - m);
    int o = bj * DD + d;
    mx[o] = m;
    inv[o] = 1.0f / s;
}

// ---------------- softmax pass B: out[b,i,d] = sum_j softmax_i(rel)[b,i,j,d]*rel ----------------
__global__ void softmax_out_kernel(const __half* __restrict__ rel,
                                   const float* __restrict__ mx,
                                   const float* __restrict__ inv,
                                   float* __restrict__ out) {
    int bi = blockIdx.x;            // b*NN + i
    int b = bi >> 7;
    int d = threadIdx.x;
    const __half* ptr = rel + (size_t)bi * NN * DD + d;
    const float* mxp = mx  + (b << 7) * DD + d;
    const float* ivp = inv + (b << 7) * DD + d;
    float acc = 0.f;
    #pragma unroll 8
    for (int j = 0; j < NN; ++j) {
        float v = __half2float(ptr[(size_t)j * DD]);
        acc += v * __expf(v - mxp[j * DD]) * ivp[j * DD];
    }
    out[bi * DD + d] = acc;
}

// ---------------- host ----------------
extern "C" void kernel_launch(void* const* d_in, const int* in_sizes, int n_in,
                              void* d_out, int out_size) {
    const float* x0   = (const float*)d_in[0];
    const float* Wrel = (const float*)d_in[1];
    const float* brel = (const float*)d_in[2];
    const float* Wgo  = (const float*)d_in[3];
    const float* bgo  = (const float*)d_in[4];
    const float* Wgr  = (const float*)d_in[5];
    const float* bgr  = (const float*)d_in[6];
    const float* Wesa = (const float*)d_in[7];
    const float* besa = (const float*)d_in[8];
    float* out = (float*)d_out;

    const float* Wra = Wrel;                 // W_rel[0:D]
    const float* Wrb = Wrel + DD*DD;         // W_rel[D:2D]
    const float* Wg1 = Wgr;                  // W_gr[0:D]
    const float* Wg2 = Wgr + DD*DD;          // W_gr[D:2D]
    const float* Wg3 = Wgr + 2*DD*DD;        // W_gr[2D:3D]

    float *bu, *bv, *bs, *bt, *bp, *bq, *bx1, *bx2, *bc, *bmx, *binv;
    __half *AH, *BH, *WgH, *WeH;
    cudaGetSymbolAddress((void**)&AH, g_AH);
    cudaGetSymbolAddress((void**)&BH, g_BH);
    cudaGetSymbolAddress((void**)&WgH, g_WgH);
    cudaGetSymbolAddress((void**)&WeH, g_WeH);
    cudaGetSymbolAddress((void**)&bu,  g_u);
    cudaGetSymbolAddress((void**)&bv,  g_v);
    cudaGetSymbolAddress((void**)&bs,  g_s);
    cudaGetSymbolAddress((void**)&bt,  g_t);
    cudaGetSymbolAddress((void**)&bp,  g_p);
    cudaGetSymbolAddress((void**)&bq,  g_q);
    cudaGetSymbolAddress((void**)&bx1, g_x1);
    cudaGetSymbolAddress((void**)&bx2, g_x2);
    cudaGetSymbolAddress((void**)&bc,  g_c);
    cudaGetSymbolAddress((void**)&bmx, g_mx);
    cudaGetSymbolAddress((void**)&binv, g_inv);

    cudaFuncSetAttribute(hgemm_kernel<0>, cudaFuncAttributeMaxDynamicSharedMemorySize, HG_SMEM);
    cudaFuncSetAttribute(hgemm_kernel<1>, cudaFuncAttributeMaxDynamicSharedMemorySize, HG_SMEM);

    dim3 bgrid(4, 256);   // 512/128 n-tiles x 32768/128 m-tiles
    dim3 tgrid(16, 16), tblk(32, 8);

    // weight transpose+f16 (independent)
    transsplit_kernel<<<tgrid, tblk>>>(Wg3,  WgH);
    transsplit_kernel<<<tgrid, tblk>>>(Wesa, WeH);

    // c = b_rel @ Wg3 + b_gr
    cvec_kernel<<<1, DD>>>(brel, Wg3, bgr, bc);

    // batch1: everything that depends only on x0
    SBatch b1 = {};
    b1.jobs[0] = { x0, Wra, nullptr, nullptr, bu,  0, 0 };   // u = x0@Wra
    b1.jobs[1] = { x0, Wrb, nullptr, nullptr, bv,  0, 0 };   // v = x0@Wrb
    b1.jobs[2] = { x0, Wg1, nullptr, nullptr, bs,  0, 0 };   // s0 = x0@Wg1
    b1.jobs[3] = { x0, Wg2, nullptr, nullptr, bt,  0, 0 };   // t0 = x0@Wg2
    b1.jobs[4] = { x0, Wgo, bgo,     nullptr, bx1, 1, 0 };   // x1 = tanh(x0@Wgo+bgo)
    sgemm_batch_kernel<<<dim3(8,8,5), 256>>>(b1);

    // batch23 merged: s += u@Wg3 ; t += v@Wg3 ; p1 ; q1 ; x2
    SBatch b23 = {};
    b23.jobs[0] = { bu,  Wg3, nullptr, bs, bs, 0, 0 };
    b23.jobs[1] = { bv,  Wg3, nullptr, bt, bt, 0, 0 };
    b23.jobs[2] = { bx1, Wg1, nullptr, nullptr, bp,  0, 0 }; // p1
    b23.jobs[3] = { bx1, Wg2, nullptr, nullptr, bq,  0, 0 }; // q1
    b23.jobs[4] = { bx1, Wgo, bgo,     nullptr, bx2, 1, 0 }; // x2
    sgemm_batch_kernel<<<dim3(8,8,5), 256>>>(b23);

    // rel1 = f16(tanh(s_i + t_j + c)) -> plane A
    init_rel_kernel<<<dim3(XROWS, 4), 256>>>(bs, bt, bc, AH);

    // rel2 = tanh(rel1@Wg3 + p1_i + q1_j + b_gr) -> plane B
    hgemm_kernel<0><<<bgrid, 256, HG_SMEM>>>(AH, WgH, bp, bq, bgr, BH);

    // batch4: layer-2 row/col terms and x3 (x3 goes straight to d_out)
    SBatch b4 = {};
    b4.jobs[0] = { bx2, Wg1, nullptr, nullptr, bp,  0, 0 };  // p2
    b4.jobs[1] = { bx2, Wg2, nullptr, nullptr, bq,  0, 0 };  // q2
    b4.jobs[2] = { bx2, Wgo, bgo,     nullptr, out, 1, 0 };  // x3 -> out[0 : B*N*D]
    sgemm_batch_kernel<<<dim3(8,8,3), 256>>>(b4);

    // rel3 = tanh(rel2@Wg3 + p2_i + q2_j + b_gr) -> plane A
    hgemm_kernel<0><<<bgrid, 256, HG_SMEM>>>(BH, WgH, bp, bq, bgr, AH);

    // rel4 = rel3@W_esa + b_esa -> fp16 plane B
    hgemm_kernel<1><<<bgrid, 256, HG_SMEM>>>(AH, WeH, nullptr, nullptr, besa, BH);

    // softmax over i, then weighted sum over j (fp16 rel input)
    softmax_stats_kernel<<<XROWS, DD>>>(BH, bmx, binv);
    softmax_out_kernel<<<XROWS, DD>>>(BH, bmx, binv, out + XROWS*DD);
}

// round 10
// speedup vs baseline: 1.0514x; 1.0514x over previous
#include <cuda_runtime.h>
#include <cuda_fp16.h>
#include <math.h>
#include <stdint.h>

#define DD 512
#define NN 128
#define BB 2
#define MBIG (BB*NN*NN)     // 32768 rows for big GEMMs
#define XROWS (BB*NN)       // 256 rows for small GEMMs

// ---------------- scratch (static device allocations; no cudaMalloc) ----------------
__device__ __half g_AH[MBIG*DD];            // rel plane A (fp16)
__device__ __half g_BH[MBIG*DD];            // rel plane B (fp16)
__device__ __half g_WgH[DD*DD];             // Wg3^T  fp16 [n][k]
__device__ __half g_WeH[DD*DD];             // Wesa^T fp16 [n][k]
__device__ float g_u [XROWS*DD];
__device__ float g_v [XROWS*DD];
__device__ float g_s [XROWS*DD];
__device__ float g_t [XROWS*DD];
__device__ float g_p [XROWS*DD];
__device__ float g_q [XROWS*DD];
__device__ float g_x1[XROWS*DD];
__device__ float g_x2[XROWS*DD];
__device__ float g_c [DD];
__device__ float g_mx [XROWS*DD];
__device__ float g_inv[XROWS*DD];

// ---------------- helpers ----------------
__device__ __forceinline__ uint32_t smem_u32(const void* p) {
    uint32_t a;
    asm("{ .reg .u64 t; cvta.to.shared.u64 t, %1; cvt.u32.u64 %0, t; }" : "=r"(a) : "l"(p));
    return a;
}
__device__ __forceinline__ void mma16816(float* c, const uint32_t* a, const uint32_t* b) {
    asm volatile(
        "mma.sync.aligned.m16n8k16.row.col.f32.f16.f16.f32 "
        "{%0,%1,%2,%3},{%4,%5,%6,%7},{%8,%9},{%0,%1,%2,%3};"
        : "+f"(c[0]), "+f"(c[1]), "+f"(c[2]), "+f"(c[3])
        : "r"(a[0]), "r"(a[1]), "r"(a[2]), "r"(a[3]), "r"(b[0]), "r"(b[1]));
}
#define LDSM4(r0,r1,r2,r3,addr) \
    asm volatile("ldmatrix.sync.aligned.m8n8.x4.shared.b16 {%0,%1,%2,%3}, [%4];" \
        : "=r"(r0),"=r"(r1),"=r"(r2),"=r"(r3) : "r"(addr))
__device__ __forceinline__ void cp16(uint32_t dst, const void* src) {
    asm volatile("cp.async.cg.shared.global [%0], [%1], 16;" :: "r"(dst), "l"(src) : "memory");
}
// fast tanh: abs err ~1e-7, saturates correctly at +/-inf
__device__ __forceinline__ float ftanh(float x) {
    float e = __expf(2.0f * x);
    return 1.0f - __fdividef(2.0f, e + 1.0f);
}

// ---------------- weight transpose+f16: out[n][k] = f16(W[k][n]) ----------------
__global__ void transsplit_kernel(const float* __restrict__ W, __half* __restrict__ Wh) {
    __shared__ float tile[32][33];
    int x = blockIdx.x * 32 + threadIdx.x;
    int y = blockIdx.y * 32 + threadIdx.y;
    #pragma unroll
    for (int r = 0; r < 32; r += 8) tile[threadIdx.y + r][threadIdx.x] = W[(y + r) * DD + x];
    __syncthreads();
    x = blockIdx.y * 32 + threadIdx.x;   // now k index
    y = blockIdx.x * 32 + threadIdx.y;   // now n index
    #pragma unroll
    for (int r = 0; r < 32; r += 8)
        Wh[(y + r) * DD + x] = __float2half_rn(tile[threadIdx.x][threadIdx.y + r]);
}

// ---------------- c = b_rel @ Wg3 + b_gr ----------------
__global__ void cvec_kernel(const float* __restrict__ b_rel,
                            const float* __restrict__ Wg3,
                            const float* __restrict__ b_gr,
                            float* __restrict__ c) {
    int d = threadIdx.x;
    float acc = b_gr[d];
    #pragma unroll 8
    for (int k = 0; k < DD; ++k)
        acc += b_rel[k] * Wg3[k*DD + d];
    c[d] = acc;
}

// ---------------- batched small GEMM (R8 variant): C = act(A@W [+bias] [+Cadd]) ----------------
struct SJob {
    const float* A; const float* W; const float* bias; const float* Cadd;
    float* C; int act; int pad;
};
struct SBatch { SJob jobs[5]; };

__global__ __launch_bounds__(256)
void sgemm_batch_kernel(SBatch batch) {
    SJob jb = batch.jobs[blockIdx.z];
    __shared__ float As[32][68];
    __shared__ float Bs[32][64];
    int t  = threadIdx.x;
    int tx = t & 15, ty = t >> 4;
    int n0 = blockIdx.x << 6, m0 = blockIdx.y << 6;
    int arow = t >> 2, aseg = (t & 3) << 3;   // 64 m-rows, 8 k-floats each
    int bk = t >> 3, bn = (t & 7) << 3;       // 32 k-rows, 8 n-floats each
    const float* Aptr = jb.A + (m0 + arow) * DD + aseg;
    const float* Bptr = jb.W + bk * DD + n0 + bn;

    float acc[4][4] = {};
    for (int kt = 0; kt < DD/32; ++kt) {
        float4 av0 = *(const float4*)(Aptr + kt*32);
        float4 av1 = *(const float4*)(Aptr + kt*32 + 4);
        float4 bv0 = *(const float4*)(Bptr + kt*32*DD);
        float4 bv1 = *(const float4*)(Bptr + kt*32*DD + 4);
        __syncthreads();
        As[aseg+0][arow]=av0.x; As[aseg+1][arow]=av0.y;
        As[aseg+2][arow]=av0.z; As[aseg+3][arow]=av0.w;
        As[aseg+4][arow]=av1.x; As[aseg+5][arow]=av1.y;
        As[aseg+6][arow]=av1.z; As[aseg+7][arow]=av1.w;
        *(float4*)&Bs[bk][bn]   = bv0;
        *(float4*)&Bs[bk][bn+4] = bv1;
        __syncthreads();
        #pragma unroll
        for (int kk = 0; kk < 32; ++kk) {
            float4 a = *(const float4*)&As[kk][ty<<2];
            float4 b = *(const float4*)&Bs[kk][tx<<2];
            acc[0][0]+=a.x*b.x; acc[0][1]+=a.x*b.y; acc[0][2]+=a.x*b.z; acc[0][3]+=a.x*b.w;
            acc[1][0]+=a.y*b.x; acc[1][1]+=a.y*b.y; acc[1][2]+=a.y*b.z; acc[1][3]+=a.y*b.w;
            acc[2][0]+=a.z*b.x; acc[2][1]+=a.z*b.y; acc[2][2]+=a.z*b.z; acc[2][3]+=a.z*b.w;
            acc[3][0]+=a.w*b.x; acc[3][1]+=a.w*b.y; acc[3][2]+=a.w*b.z; acc[3][3]+=a.w*b.w;
        }
    }
    int n = n0 + (tx<<2);
    float4 bb = make_float4(0.f, 0.f, 0.f, 0.f);
    if (jb.bias) bb = *(const float4*)(jb.bias + n);
    #pragma unroll
    for (int mm = 0; mm < 4; ++mm) {
        int m = m0 + (ty<<2) + mm;
        float4 r = make_float4(acc[mm][0]+bb.x, acc[mm][1]+bb.y,
                               acc[mm][2]+bb.z, acc[mm][3]+bb.w);
        if (jb.Cadd) {
            float4 cv = *(const float4*)(jb.Cadd + m*DD + n);
            r.x += cv.x; r.y += cv.y; r.z += cv.z; r.w += cv.w;
        }
        if (jb.act) { r.x=ftanh(r.x); r.y=ftanh(r.y); r.z=ftanh(r.z); r.w=ftanh(r.w); }
        *(float4*)&jb.C[m*DD + n] = r;
    }
}

// ---------------- rel1 init: f16(tanh(s_i + t_j + c)) ----------------
__global__ __launch_bounds__(256)
void init_rel_kernel(const float* __restrict__ s, const float* __restrict__ t,
                     const float* __restrict__ c, __half* __restrict__ RH) {
    __shared__ float srow[DD];
    int bi = blockIdx.x;                 // b*128 + i
    int b  = bi >> 7;
    int tid = threadIdx.x;
    #pragma unroll
    for (int d = tid; d < DD; d += 256) srow[d] = s[bi * DD + d] + c[d];
    __syncthreads();
    int j0 = blockIdx.y * 32;
    int d = tid * 2;
    for (int j = j0; j < j0 + 32; ++j) {
        const float* trow = t + (size_t)((b << 7) + j) * DD;
        float v0 = ftanh(srow[d]   + trow[d]);
        float v1 = ftanh(srow[d+1] + trow[d+1]);
        size_t m = (size_t)bi * NN + j;
        *(__half2*)&RH[m * DD + d] = __halves2half2(__float2half_rn(v0), __float2half_rn(v1));
    }
}

// ================= big GEMM via mma.sync (fp16, 3-stage cp.async ring) =================
// C[32768,512] = A @ Wt^T. Per-CTA tile 128x128, K chunks of 32, 3 smem stages.
// Stage layout (row stride 80B = 64 data + 16 pad): A +0, B +10240; stage 20480 B.
// MODE 0: v = tanh(D + P[b,i,:] + Q[b,j,:] + bias) -> Chi (fp16)
// MODE 1: v = D + bias -> Chi (fp16)
#define HG_SMEM (3*20480)

template<int MODE>
__global__ __launch_bounds__(256, 2)
void hgemm_kernel(const __half* __restrict__ Ah, const __half* __restrict__ Bh,
                  const float* __restrict__ P, const float* __restrict__ Q,
                  const float* __restrict__ bias, __half* __restrict__ Chi) {
    extern __shared__ __align__(16) char sm[];
    const uint32_t smBase = smem_u32(sm);
    const int tid = threadIdx.x;
    const int n0 = blockIdx.x << 7, m0 = blockIdx.y << 7;

    // --- cp.async: 2 groups of 128 threads; each thread one row (64 B = 4 x 16B) ---
    const int mat = tid >> 7, tt = tid & 127;
    const __half* plane = mat ? (Bh + (size_t)(n0 + tt) * DD) : (Ah + (size_t)(m0 + tt) * DD);
    const uint32_t dstoff = (uint32_t)mat * 10240u + (uint32_t)tt * 80u;

    const int lane = tid & 31, wid = tid >> 5;
    const int g = lane >> 2, q = lane & 3;
    const int wm = (wid & 1) * 64, wn = (wid >> 1) * 32;

    // ldmatrix lane addressing
    const int lr = lane & 7, sub = lane >> 3;
    const uint32_t rowsel = (uint32_t)((sub & 1) * 8 + lr);
    const uint32_t colsel = (uint32_t)((sub >> 1) * 16);
    const uint32_t aoff = (uint32_t)(wm + rowsel) * 80u + colsel;            // + mt*1280 + ks*32
    const uint32_t boff = 10240u + (uint32_t)(wn + rowsel) * 80u + colsel;   // + ntp*1280 + ks*32

    const uint32_t stage0 = smBase, stage1 = smBase + 20480u, stage2 = smBase + 40960u;

    float cacc[4][4][4];
    #pragma unroll
    for (int a = 0; a < 4; ++a)
        #pragma unroll
        for (int b = 0; b < 4; ++b)
            #pragma unroll
            for (int e = 0; e < 4; ++e) cacc[a][b][e] = 0.f;

    // prologue: chunks 0 -> stage0, 1 -> stage1
    {
        uint32_t d = stage0 + dstoff;
        #pragma unroll
        for (int sg = 0; sg < 4; ++sg) cp16(d + sg*16, plane + sg*8);
        asm volatile("cp.async.commit_group;" ::: "memory");
        d = stage1 + dstoff;
        const __half* sp = plane + 32;
        #pragma unroll
        for (int sg = 0; sg < 4; ++sg) cp16(d + sg*16, sp + sg*8);
        asm volatile("cp.async.commit_group;" ::: "memory");
    }

    uint32_t stComp = stage0, stLoad = stage2;   // compute stage for kc, load target for kc+2
    for (int kc = 0; kc < 16; ++kc) {
        if (kc < 15) asm volatile("cp.async.wait_group 1;" ::: "memory");
        else         asm volatile("cp.async.wait_group 0;" ::: "memory");
        __syncthreads();   // chunk kc visible to all; all warps done computing chunk kc-1

        if (kc + 2 < 16) {
            uint32_t d = stLoad + dstoff;
            const __half* sp = plane + (kc + 2) * 32;
            #pragma unroll
            for (int sg = 0; sg < 4; ++sg) cp16(d + sg*16, sp + sg*8);
            asm volatile("cp.async.commit_group;" ::: "memory");
        }

        uint32_t bufb = stComp;
        #pragma unroll
        for (int ks = 0; ks < 2; ++ks) {
            uint32_t kso = (uint32_t)(ks * 32);
            uint32_t bfh[4][2];
            #pragma unroll
            for (int ntp = 0; ntp < 2; ++ntp) {
                uint32_t ba = bufb + boff + (uint32_t)ntp * 1280u + kso;
                uint32_t r0, r1, r2, r3;
                LDSM4(r0, r1, r2, r3, ba);
                bfh[2*ntp][0]=r0; bfh[2*ntp+1][0]=r1; bfh[2*ntp][1]=r2; bfh[2*ntp+1][1]=r3;
            }
            #pragma unroll
            for (int mt = 0; mt < 4; ++mt) {
                uint32_t aa = bufb + aoff + (uint32_t)mt * 1280u + kso;
                uint32_t ah[4];
                LDSM4(ah[0], ah[1], ah[2], ah[3], aa);
                #pragma unroll
                for (int nt = 0; nt < 4; ++nt)
                    mma16816(cacc[mt][nt], ah, bfh[nt]);
            }
        }
        // rotate stages: comp kc+1 = old (kc+1)%3, load target = freed stage
        uint32_t newComp = (stComp == stage2) ? stage0 : stComp + 20480u;
        stLoad = stComp;
        stComp = newComp;
    }

    // ---- epilogue ----
    #pragma unroll
    for (int mt = 0; mt < 4; ++mt) {
        #pragma unroll
        for (int nt = 0; nt < 4; ++nt) {
            int col = n0 + wn + nt*8 + q*2;
            float b0 = bias[col], b1 = bias[col + 1];
            #pragma unroll
            for (int rh = 0; rh < 2; ++rh) {
                int r = m0 + wm + mt*16 + g + rh*8;
                float v0 = cacc[mt][nt][rh*2 + 0] + b0;
                float v1 = cacc[mt][nt][rh*2 + 1] + b1;
                if (MODE == 0) {
                    int b = r >> 14, ii = (r >> 7) & 127, jj = r & 127;
                    const float* pr = P + (size_t)(((b<<7)+ii)) * DD;
                    const float* qr = Q + (size_t)(((b<<7)+jj)) * DD;
                    v0 = ftanh(v0 + pr[col]   + qr[col]);
                    v1 = ftanh(v1 + pr[col+1] + qr[col+1]);
                }
                *(__half2*)&Chi[(size_t)r * DD + col] =
                    __halves2half2(__float2half_rn(v0), __float2half_rn(v1));
            }
        }
    }
}

// ---------------- softmax pass A: per (b,j,d) max & 1/sumexp over i (fp16 rel) ----------------
__global__ void softmax_stats_kernel(const __half* __restrict__ rel,
                                     float* __restrict__ mx, float* __restrict__ inv) {
    int bj = blockIdx.x;            // b*NN + j
    int b = bj >> 7, j = bj & 127;
    int d = threadIdx.x;
    const __half* ptr = rel + (size_t)((b << 14) + j) * DD + d;
    float m = -1e30f;
    #pragma unroll 8
    for (int i = 0; i < NN; ++i) m = fmaxf(m, __half2float(ptr[(size_t)i * NN * DD]));
    float s = 0.f;
    #pragma unroll 8
    for (int i = 0; i < NN; ++i) s += __expf(__half2float(ptr[(size_t)i * NN * DD]) - m);
    int o = bj * DD + d;
    mx[o] = m;
    inv[o] = 1.0f / s;
}

// ---------------- softmax pass B: out[b,i,d] = sum_j softmax_i(rel)[b,i,j,d]*rel ----------------
__global__ void softmax_out_kernel(const __half* __restrict__ rel,
                                   const float* __restrict__ mx,
                                   const float* __restrict__ inv,
                                   float* __restrict__ out) {
    int bi = blockIdx.x;            // b*NN + i
    int b = bi >> 7;
    int d = threadIdx.x;
    const __half* ptr = rel + (size_t)bi * NN * DD + d;
    const float* mxp = mx  + (b << 7) * DD + d;
    const float* ivp = inv + (b << 7) * DD + d;
    float acc = 0.f;
    #pragma unroll 8
    for (int j = 0; j < NN; ++j) {
        float v = __half2float(ptr[(size_t)j * DD]);
        acc += v * __expf(v - mxp[j * DD]) * ivp[j * DD];
    }
    out[bi * DD + d] = acc;
}

// ---------------- host ----------------
extern "C" void kernel_launch(void* const* d_in, const int* in_sizes, int n_in,
                              void* d_out, int out_size) {
    const float* x0   = (const float*)d_in[0];
    const float* Wrel = (const float*)d_in[1];
    const float* brel = (const float*)d_in[2];
    const float* Wgo  = (const float*)d_in[3];
    const float* bgo  = (const float*)d_in[4];
    const float* Wgr  = (const float*)d_in[5];
    const float* bgr  = (const float*)d_in[6];
    const float* Wesa = (const float*)d_in[7];
    const float* besa = (const float*)d_in[8];
    float* out = (float*)d_out;

    const float* Wra = Wrel;                 // W_rel[0:D]
    const float* Wrb = Wrel + DD*DD;         // W_rel[D:2D]
    const float* Wg1 = Wgr;                  // W_gr[0:D]
    const float* Wg2 = Wgr + DD*DD;          // W_gr[D:2D]
    const float* Wg3 = Wgr + 2*DD*DD;        // W_gr[2D:3D]

    float *bu, *bv, *bs, *bt, *bp, *bq, *bx1, *bx2, *bc, *bmx, *binv;
    __half *AH, *BH, *WgH, *WeH;
    cudaGetSymbolAddress((void**)&AH, g_AH);
    cudaGetSymbolAddress((void**)&BH, g_BH);
    cudaGetSymbolAddress((void**)&WgH, g_WgH);
    cudaGetSymbolAddress((void**)&WeH, g_WeH);
    cudaGetSymbolAddress((void**)&bu,  g_u);
    cudaGetSymbolAddress((void**)&bv,  g_v);
    cudaGetSymbolAddress((void**)&bs,  g_s);
    cudaGetSymbolAddress((void**)&bt,  g_t);
    cudaGetSymbolAddress((void**)&bp,  g_p);
    cudaGetSymbolAddress((void**)&bq,  g_q);
    cudaGetSymbolAddress((void**)&bx1, g_x1);
    cudaGetSymbolAddress((void**)&bx2, g_x2);
    cudaGetSymbolAddress((void**)&bc,  g_c);
    cudaGetSymbolAddress((void**)&bmx, g_mx);
    cudaGetSymbolAddress((void**)&binv, g_inv);

    cudaFuncSetAttribute(hgemm_kernel<0>, cudaFuncAttributeMaxDynamicSharedMemorySize, HG_SMEM);
    cudaFuncSetAttribute(hgemm_kernel<1>, cudaFuncAttributeMaxDynamicSharedMemorySize, HG_SMEM);

    dim3 bgrid(4, 256);   // 512/128 n-tiles x 32768/128 m-tiles
    dim3 tgrid(16, 16), tblk(32, 8);

    // weight transpose+f16 (independent)
    transsplit_kernel<<<tgrid, tblk>>>(Wg3,  WgH);
    transsplit_kernel<<<tgrid, tblk>>>(Wesa, WeH);

    // c = b_rel @ Wg3 + b_gr
    cvec_kernel<<<1, DD>>>(brel, Wg3, bgr, bc);

    // batch1: everything that depends only on x0
    SBatch b1 = {};
    b1.jobs[0] = { x0, Wra, nullptr, nullptr, bu,  0, 0 };   // u = x0@Wra
    b1.jobs[1] = { x0, Wrb, nullptr, nullptr, bv,  0, 0 };   // v = x0@Wrb
    b1.jobs[2] = { x0, Wg1, nullptr, nullptr, bs,  0, 0 };   // s0 = x0@Wg1
    b1.jobs[3] = { x0, Wg2, nullptr, nullptr, bt,  0, 0 };   // t0 = x0@Wg2
    b1.jobs[4] = { x0, Wgo, bgo,     nullptr, bx1, 1, 0 };   // x1 = tanh(x0@Wgo+bgo)
    sgemm_batch_kernel<<<dim3(8,4,5), 256>>>(b1);

    // batch23 merged: s += u@Wg3 ; t += v@Wg3 ; p1 ; q1 ; x2
    SBatch b23 = {};
    b23.jobs[0] = { bu,  Wg3, nullptr, bs, bs, 0, 0 };
    b23.jobs[1] = { bv,  Wg3, nullptr, bt, bt, 0, 0 };
    b23.jobs[2] = { bx1, Wg1, nullptr, nullptr, bp,  0, 0 }; // p1
    b23.jobs[3] = { bx1, Wg2, nullptr, nullptr, bq,  0, 0 }; // q1
    b23.jobs[4] = { bx1, Wgo, bgo,     nullptr, bx2, 1, 0 }; // x2
    sgemm_batch_kernel<<<dim3(8,4,5), 256>>>(b23);

    // rel1 = f16(tanh(s_i + t_j + c)) -> plane A
    init_rel_kernel<<<dim3(XROWS, 4), 256>>>(bs, bt, bc, AH);

    // rel2 = tanh(rel1@Wg3 + p1_i + q1_j + b_gr) -> plane B
    hgemm_kernel<0><<<bgrid, 256, HG_SMEM>>>(AH, WgH, bp, bq, bgr, BH);

    // batch4: layer-2 row/col terms and x3 (x3 goes straight to d_out)
    SBatch b4 = {};
    b4.jobs[0] = { bx2, Wg1, nullptr, nullptr, bp,  0, 0 };  // p2
    b4.jobs[1] = { bx2, Wg2, nullptr, nullptr, bq,  0, 0 };  // q2
    b4.jobs[2] = { bx2, Wgo, bgo,     nullptr, out, 1, 0 };  // x3 -> out[0 : B*N*D]
    sgemm_batch_kernel<<<dim3(8,4,3), 256>>>(b4);

    // rel3 = tanh(rel2@Wg3 + p2_i + q2_j + b_gr) -> plane A
    hgemm_kernel<0><<<bgrid, 256, HG_SMEM>>>(BH, WgH, bp, bq, bgr, AH);

    // rel4 = rel3@W_esa + b_esa -> fp16 plane B
    hgemm_kernel<1><<<bgrid, 256, HG_SMEM>>>(AH, WeH, nullptr, nullptr, besa, BH);

    // softmax over i, then weighted sum over j (fp16 rel input)
    softmax_stats_kernel<<<XROWS, DD>>>(BH, bmx, binv);
    softmax_out_kernel<<<XROWS, DD>>>(BH, bmx, binv, out + XROWS*DD);
}

// round 11
// speedup vs baseline: 1.0651x; 1.0130x over previous
#include <cuda_runtime.h>
#include <cuda_fp16.h>
#include <math.h>
#include <stdint.h>

#define DD 512
#define NN 128
#define BB 2
#define MBIG (BB*NN*NN)     // 32768 rows for big GEMMs
#define XROWS (BB*NN)       // 256 rows for small GEMMs

// ---------------- scratch (static device allocations; no cudaMalloc) ----------------
__device__ __half g_AH[MBIG*DD];            // rel plane A (fp16)
__device__ __half g_BH[MBIG*DD];            // rel plane B (fp16)
__device__ __half g_WgH[DD*DD];             // Wg3^T  fp16 [n][k]
__device__ __half g_WeH[DD*DD];             // Wesa^T fp16 [n][k]
__device__ float g_u [XROWS*DD];
__device__ float g_v [XROWS*DD];
__device__ float g_s [XROWS*DD];
__device__ float g_t [XROWS*DD];
__device__ float g_p [XROWS*DD];
__device__ float g_q [XROWS*DD];
__device__ float g_x1[XROWS*DD];
__device__ float g_x2[XROWS*DD];
__device__ float g_c [DD];
__device__ float g_mx [XROWS*DD];
__device__ float g_inv[XROWS*DD];

// ---------------- helpers ----------------
__device__ __forceinline__ uint32_t smem_u32(const void* p) {
    uint32_t a;
    asm("{ .reg .u64 t; cvta.to.shared.u64 t, %1; cvt.u32.u64 %0, t; }" : "=r"(a) : "l"(p));
    return a;
}
__device__ __forceinline__ void mma16816(float* c, const uint32_t* a, const uint32_t* b) {
    asm volatile(
        "mma.sync.aligned.m16n8k16.row.col.f32.f16.f16.f32 "
        "{%0,%1,%2,%3},{%4,%5,%6,%7},{%8,%9},{%0,%1,%2,%3};"
        : "+f"(c[0]), "+f"(c[1]), "+f"(c[2]), "+f"(c[3])
        : "r"(a[0]), "r"(a[1]), "r"(a[2]), "r"(a[3]), "r"(b[0]), "r"(b[1]));
}
#define LDSM4(r0,r1,r2,r3,addr) \
    asm volatile("ldmatrix.sync.aligned.m8n8.x4.shared.b16 {%0,%1,%2,%3}, [%4];" \
        : "=r"(r0),"=r"(r1),"=r"(r2),"=r"(r3) : "r"(addr))
__device__ __forceinline__ void cp16(uint32_t dst, const void* src) {
    asm volatile("cp.async.cg.shared.global [%0], [%1], 16;" :: "r"(dst), "l"(src) : "memory");
}
// fast tanh: abs err ~1e-7, saturates correctly at +/-inf
__device__ __forceinline__ float ftanh(float x) {
    float e = __expf(2.0f * x);
    return 1.0f - __fdividef(2.0f, e + 1.0f);
}

// ---------------- weight transpose+f16 (both weights in one launch) ----------------
__global__ void transsplit_kernel(const float* __restrict__ W0, __half* __restrict__ Wh0,
                                  const float* __restrict__ W1, __half* __restrict__ Wh1) {
    const float* W  = blockIdx.z ? W1  : W0;
    __half*      Wh = blockIdx.z ? Wh1 : Wh0;
    __shared__ float tile[32][33];
    int x = blockIdx.x * 32 + threadIdx.x;
    int y = blockIdx.y * 32 + threadIdx.y;
    #pragma unroll
    for (int r = 0; r < 32; r += 8) tile[threadIdx.y + r][threadIdx.x] = W[(y + r) * DD + x];
    __syncthreads();
    x = blockIdx.y * 32 + threadIdx.x;   // now k index
    y = blockIdx.x * 32 + threadIdx.y;   // now n index
    #pragma unroll
    for (int r = 0; r < 32; r += 8)
        Wh[(y + r) * DD + x] = __float2half_rn(tile[threadIdx.x][threadIdx.y + r]);
}

// ---------------- c = b_rel @ Wg3 + b_gr ----------------
__global__ void cvec_kernel(const float* __restrict__ b_rel,
                            const float* __restrict__ Wg3,
                            const float* __restrict__ b_gr,
                            float* __restrict__ c) {
    int d = threadIdx.x;
    float acc = b_gr[d];
    #pragma unroll 8
    for (int k = 0; k < DD; ++k)
        acc += b_rel[k] * Wg3[k*DD + d];
    c[d] = acc;
}

// ---------------- batched small GEMM (reg-prefetch pipeline): C = act(A@W [+bias] [+Cadd]) ----------------
struct SJob {
    const float* A; const float* W; const float* bias; const float* Cadd;
    float* C; int act; int pad;
};
struct SBatch { SJob jobs[5]; };

__global__ __launch_bounds__(256)
void sgemm_batch_kernel(SBatch batch) {
    SJob jb = batch.jobs[blockIdx.z];
    __shared__ float As[32][68];
    __shared__ float Bs[32][64];
    int t  = threadIdx.x;
    int tx = t & 15, ty = t >> 4;
    int n0 = blockIdx.x << 6, m0 = blockIdx.y << 6;
    int arow = t >> 2, aseg = (t & 3) << 3;   // 64 m-rows, 8 k-floats each
    int bk = t >> 3, bn = (t & 7) << 3;       // 32 k-rows, 8 n-floats each
    const float* Aptr = jb.A + (m0 + arow) * DD + aseg;
    const float* Bptr = jb.W + bk * DD + n0 + bn;

    // preload chunk 0 into registers
    float4 av0 = *(const float4*)(Aptr);
    float4 av1 = *(const float4*)(Aptr + 4);
    float4 bv0 = *(const float4*)(Bptr);
    float4 bv1 = *(const float4*)(Bptr + 4);

    float acc[4][4] = {};
    for (int kt = 0; kt < DD/32; ++kt) {
        __syncthreads();          // previous compute finished reading smem
        As[aseg+0][arow]=av0.x; As[aseg+1][arow]=av0.y;
        As[aseg+2][arow]=av0.z; As[aseg+3][arow]=av0.w;
        As[aseg+4][arow]=av1.x; As[aseg+5][arow]=av1.y;
        As[aseg+6][arow]=av1.z; As[aseg+7][arow]=av1.w;
        *(float4*)&Bs[bk][bn]   = bv0;
        *(float4*)&Bs[bk][bn+4] = bv1;
        __syncthreads();
        if (kt < DD/32 - 1) {     // issue loads for kt+1; latency hidden by compute below
            av0 = *(const float4*)(Aptr + (kt+1)*32);
            av1 = *(const float4*)(Aptr + (kt+1)*32 + 4);
            bv0 = *(const float4*)(Bptr + (kt+1)*32*DD);
            bv1 = *(const float4*)(Bptr + (kt+1)*32*DD + 4);
        }
        #pragma unroll
        for (int kk = 0; kk < 32; ++kk) {
            float4 a = *(const float4*)&As[kk][ty<<2];
            float4 b = *(const float4*)&Bs[kk][tx<<2];
            acc[0][0]+=a.x*b.x; acc[0][1]+=a.x*b.y; acc[0][2]+=a.x*b.z; acc[0][3]+=a.x*b.w;
            acc[1][0]+=a.y*b.x; acc[1][1]+=a.y*b.y; acc[1][2]+=a.y*b.z; acc[1][3]+=a.y*b.w;
            acc[2][0]+=a.z*b.x; acc[2][1]+=a.z*b.y; acc[2][2]+=a.z*b.z; acc[2][3]+=a.z*b.w;
            acc[3][0]+=a.w*b.x; acc[3][1]+=a.w*b.y; acc[3][2]+=a.w*b.z; acc[3][3]+=a.w*b.w;
        }
    }
    int n = n0 + (tx<<2);
    float4 bb = make_float4(0.f, 0.f, 0.f, 0.f);
    if (jb.bias) bb = *(const float4*)(jb.bias + n);
    #pragma unroll
    for (int mm = 0; mm < 4; ++mm) {
        int m = m0 + (ty<<2) + mm;
        float4 r = make_float4(acc[mm][0]+bb.x, acc[mm][1]+bb.y,
                               acc[mm][2]+bb.z, acc[mm][3]+bb.w);
        if (jb.Cadd) {
            float4 cv = *(const float4*)(jb.Cadd + m*DD + n);
            r.x += cv.x; r.y += cv.y; r.z += cv.z; r.w += cv.w;
        }
        if (jb.act) { r.x=ftanh(r.x); r.y=ftanh(r.y); r.z=ftanh(r.z); r.w=ftanh(r.w); }
        *(float4*)&jb.C[m*DD + n] = r;
    }
}

// ---------------- rel1 init: f16(tanh(s_i + t_j + c)) ----------------
__global__ __launch_bounds__(256)
void init_rel_kernel(const float* __restrict__ s, const float* __restrict__ t,
                     const float* __restrict__ c, __half* __restrict__ RH) {
    __shared__ float srow[DD];
    int bi = blockIdx.x;                 // b*128 + i
    int b  = bi >> 7;
    int tid = threadIdx.x;
    #pragma unroll
    for (int d = tid; d < DD; d += 256) srow[d] = s[bi * DD + d] + c[d];
    __syncthreads();
    int j0 = blockIdx.y * 32;
    int d = tid * 2;
    for (int j = j0; j < j0 + 32; ++j) {
        const float* trow = t + (size_t)((b << 7) + j) * DD;
        float v0 = ftanh(srow[d]   + trow[d]);
        float v1 = ftanh(srow[d+1] + trow[d+1]);
        size_t m = (size_t)bi * NN + j;
        *(__half2*)&RH[m * DD + d] = __halves2half2(__float2half_rn(v0), __float2half_rn(v1));
    }
}

// ================= big GEMM via mma.sync (fp16, 3-stage cp.async ring) =================
// C[32768,512] = A @ Wt^T. Per-CTA tile 128x128, K chunks of 32, 3 smem stages.
// Stage layout (row stride 80B = 64 data + 16 pad): A +0, B +10240; stage 20480 B.
// MODE 0: v = tanh(D + P[b,i,:] + Q[b,j,:] + bias) -> Chi (fp16)
// MODE 1: v = D + bias -> Chi (fp16)
#define HG_SMEM (3*20480)

template<int MODE>
__global__ __launch_bounds__(256, 2)
void hgemm_kernel(const __half* __restrict__ Ah, const __half* __restrict__ Bh,
                  const float* __restrict__ P, const float* __restrict__ Q,
                  const float* __restrict__ bias, __half* __restrict__ Chi) {
    extern __shared__ __align__(16) char sm[];
    const uint32_t smBase = smem_u32(sm);
    const int tid = threadIdx.x;
    const int n0 = blockIdx.x << 7, m0 = blockIdx.y << 7;

    // --- cp.async: 2 groups of 128 threads; each thread one row (64 B = 4 x 16B) ---
    const int mat = tid >> 7, tt = tid & 127;
    const __half* plane = mat ? (Bh + (size_t)(n0 + tt) * DD) : (Ah + (size_t)(m0 + tt) * DD);
    const uint32_t dstoff = (uint32_t)mat * 10240u + (uint32_t)tt * 80u;

    const int lane = tid & 31, wid = tid >> 5;
    const int g = lane >> 2, q = lane & 3;
    const int wm = (wid & 1) * 64, wn = (wid >> 1) * 32;

    // ldmatrix lane addressing
    const int lr = lane & 7, sub = lane >> 3;
    const uint32_t rowsel = (uint32_t)((sub & 1) * 8 + lr);
    const uint32_t colsel = (uint32_t)((sub >> 1) * 16);
    const uint32_t aoff = (uint32_t)(wm + rowsel) * 80u + colsel;            // + mt*1280 + ks*32
    const uint32_t boff = 10240u + (uint32_t)(wn + rowsel) * 80u + colsel;   // + ntp*1280 + ks*32

    const uint32_t stage0 = smBase, stage1 = smBase + 20480u, stage2 = smBase + 40960u;

    float cacc[4][4][4];
    #pragma unroll
    for (int a = 0; a < 4; ++a)
        #pragma unroll
        for (int b = 0; b < 4; ++b)
            #pragma unroll
            for (int e = 0; e < 4; ++e) cacc[a][b][e] = 0.f;

    // prologue: chunks 0 -> stage0, 1 -> stage1
    {
        uint32_t d = stage0 + dstoff;
        #pragma unroll
        for (int sg = 0; sg < 4; ++sg) cp16(d + sg*16, plane + sg*8);
        asm volatile("cp.async.commit_group;" ::: "memory");
        d = stage1 + dstoff;
        const __half* sp = plane + 32;
        #pragma unroll
        for (int sg = 0; sg < 4; ++sg) cp16(d + sg*16, sp + sg*8);
        asm volatile("cp.async.commit_group;" ::: "memory");
    }

    uint32_t stComp = stage0, stLoad = stage2;   // compute stage for kc, load target for kc+2
    for (int kc = 0; kc < 16; ++kc) {
        if (kc < 15) asm volatile("cp.async.wait_group 1;" ::: "memory");
        else         asm volatile("cp.async.wait_group 0;" ::: "memory");
        __syncthreads();   // chunk kc visible to all; all warps done computing chunk kc-1

        if (kc + 2 < 16) {
            uint32_t d = stLoad + dstoff;
            const __half* sp = plane + (kc + 2) * 32;
            #pragma unroll
            for (int sg = 0; sg < 4; ++sg) cp16(d + sg*16, sp + sg*8);
            asm volatile("cp.async.commit_group;" ::: "memory");
        }

        uint32_t bufb = stComp;
        #pragma unroll
        for (int ks = 0; ks < 2; ++ks) {
            uint32_t kso = (uint32_t)(ks * 32);
            uint32_t bfh[4][2];
            #pragma unroll
            for (int ntp = 0; ntp < 2; ++ntp) {
                uint32_t ba = bufb + boff + (uint32_t)ntp * 1280u + kso;
                uint32_t r0, r1, r2, r3;
                LDSM4(r0, r1, r2, r3, ba);
                bfh[2*ntp][0]=r0; bfh[2*ntp+1][0]=r1; bfh[2*ntp][1]=r2; bfh[2*ntp+1][1]=r3;
            }
            #pragma unroll
            for (int mt = 0; mt < 4; ++mt) {
                uint32_t aa = bufb + aoff + (uint32_t)mt * 1280u + kso;
                uint32_t ah[4];
                LDSM4(ah[0], ah[1], ah[2], ah[3], aa);
                #pragma unroll
                for (int nt = 0; nt < 4; ++nt)
                    mma16816(cacc[mt][nt], ah, bfh[nt]);
            }
        }
        // rotate stages
        uint32_t newComp = (stComp == stage2) ? stage0 : stComp + 20480u;
        stLoad = stComp;
        stComp = newComp;
    }

    // ---- epilogue ----
    #pragma unroll
    for (int mt = 0; mt < 4; ++mt) {
        #pragma unroll
        for (int nt = 0; nt < 4; ++nt) {
            int col = n0 + wn + nt*8 + q*2;
            float b0 = bias[col], b1 = bias[col + 1];
            #pragma unroll
            for (int rh = 0; rh < 2; ++rh) {
                int r = m0 + wm + mt*16 + g + rh*8;
                float v0 = cacc[mt][nt][rh*2 + 0] + b0;
                float v1 = cacc[mt][nt][rh*2 + 1] + b1;
                if (MODE == 0) {
                    int b = r >> 14, ii = (r >> 7) & 127, jj = r & 127;
                    const float* pr = P + (size_t)(((b<<7)+ii)) * DD;
                    const float* qr = Q + (size_t)(((b<<7)+jj)) * DD;
                    v0 = ftanh(v0 + pr[col]   + qr[col]);
                    v1 = ftanh(v1 + pr[col+1] + qr[col+1]);
                }
                *(__half2*)&Chi[(size_t)r * DD + col] =
                    __halves2half2(__float2half_rn(v0), __float2half_rn(v1));
            }
        }
    }
}

// ---------------- softmax pass A: per (b,j,d) max & 1/sumexp over i (fp16 rel) ----------------
__global__ void softmax_stats_kernel(const __half* __restrict__ rel,
                                     float* __restrict__ mx, float* __restrict__ inv) {
    int bj = blockIdx.x;            // b*NN + j
    int b = bj >> 7, j = bj & 127;
    int d = threadIdx.x;
    const __half* ptr = rel + (size_t)((b << 14) + j) * DD + d;
    float m = -1e30f;
    #pragma unroll 8
    for (int i = 0; i < NN; ++i) m = fmaxf(m, __half2float(ptr[(size_t)i * NN * DD]));
    float s = 0.f;
    #pragma unroll 8
    for (int i = 0; i < NN; ++i) s += __expf(__half2float(ptr[(size_t)i * NN * DD]) - m);
    int o = bj * DD + d;
    mx[o] = m;
    inv[o] = 1.0f / s;
}

// ---------------- softmax pass B: out[b,i,d] = sum_j softmax_i(rel)[b,i,j,d]*rel ----------------
__global__ void softmax_out_kernel(const __half* __restrict__ rel,
                                   const float* __restrict__ mx,
                                   const float* __restrict__ inv,
                                   float* __restrict__ out) {
    int bi = blockIdx.x;            // b*NN + i
    int b = bi >> 7;
    int d = threadIdx.x;
    const __half* ptr = rel + (size_t)bi * NN * DD + d;
    const float* mxp = mx  + (b << 7) * DD + d;
    const float* ivp = inv + (b << 7) * DD + d;
    float acc = 0.f;
    #pragma unroll 8
    for (int j = 0; j < NN; ++j) {
        float v = __half2float(ptr[(size_t)j * DD]);
        acc += v * __expf(v - mxp[j * DD]) * ivp[j * DD];
    }
    out[bi * DD + d] = acc;
}

// ---------------- host ----------------
extern "C" void kernel_launch(void* const* d_in, const int* in_sizes, int n_in,
                              void* d_out, int out_size) {
    const float* x0   = (const float*)d_in[0];
    const float* Wrel = (const float*)d_in[1];
    const float* brel = (const float*)d_in[2];
    const float* Wgo  = (const float*)d_in[3];
    const float* bgo  = (const float*)d_in[4];
    const float* Wgr  = (const float*)d_in[5];
    const float* bgr  = (const float*)d_in[6];
    const float* Wesa = (const float*)d_in[7];
    const float* besa = (const float*)d_in[8];
    float* out = (float*)d_out;

    const float* Wra = Wrel;                 // W_rel[0:D]
    const float* Wrb = Wrel + DD*DD;         // W_rel[D:2D]
    const float* Wg1 = Wgr;                  // W_gr[0:D]
    const float* Wg2 = Wgr + DD*DD;          // W_gr[D:2D]
    const float* Wg3 = Wgr + 2*DD*DD;        // W_gr[2D:3D]

    float *bu, *bv, *bs, *bt, *bp, *bq, *bx1, *bx2, *bc, *bmx, *binv;
    __half *AH, *BH, *WgH, *WeH;
    cudaGetSymbolAddress((void**)&AH, g_AH);
    cudaGetSymbolAddress((void**)&BH, g_BH);
    cudaGetSymbolAddress((void**)&WgH, g_WgH);
    cudaGetSymbolAddress((void**)&WeH, g_WeH);
    cudaGetSymbolAddress((void**)&bu,  g_u);
    cudaGetSymbolAddress((void**)&bv,  g_v);
    cudaGetSymbolAddress((void**)&bs,  g_s);
    cudaGetSymbolAddress((void**)&bt,  g_t);
    cudaGetSymbolAddress((void**)&bp,  g_p);
    cudaGetSymbolAddress((void**)&bq,  g_q);
    cudaGetSymbolAddress((void**)&bx1, g_x1);
    cudaGetSymbolAddress((void**)&bx2, g_x2);
    cudaGetSymbolAddress((void**)&bc,  g_c);
    cudaGetSymbolAddress((void**)&bmx, g_mx);
    cudaGetSymbolAddress((void**)&binv, g_inv);

    cudaFuncSetAttribute(hgemm_kernel<0>, cudaFuncAttributeMaxDynamicSharedMemorySize, HG_SMEM);
    cudaFuncSetAttribute(hgemm_kernel<1>, cudaFuncAttributeMaxDynamicSharedMemorySize, HG_SMEM);

    dim3 bgrid(4, 256);   // 512/128 n-tiles x 32768/128 m-tiles
    dim3 tgrid(16, 16, 2), tblk(32, 8);

    // both weight transposes in one launch
    transsplit_kernel<<<tgrid, tblk>>>(Wg3, WgH, Wesa, WeH);

    // c = b_rel @ Wg3 + b_gr
    cvec_kernel<<<1, DD>>>(brel, Wg3, bgr, bc);

    // batch1: everything that depends only on x0
    SBatch b1 = {};
    b1.jobs[0] = { x0, Wra, nullptr, nullptr, bu,  0, 0 };   // u = x0@Wra
    b1.jobs[1] = { x0, Wrb, nullptr, nullptr, bv,  0, 0 };   // v = x0@Wrb
    b1.jobs[2] = { x0, Wg1, nullptr, nullptr, bs,  0, 0 };   // s0 = x0@Wg1
    b1.jobs[3] = { x0, Wg2, nullptr, nullptr, bt,  0, 0 };   // t0 = x0@Wg2
    b1.jobs[4] = { x0, Wgo, bgo,     nullptr, bx1, 1, 0 };   // x1 = tanh(x0@Wgo+bgo)
    sgemm_batch_kernel<<<dim3(8,4,5), 256>>>(b1);

    // batch23 merged: s += u@Wg3 ; t += v@Wg3 ; p1 ; q1 ; x2
    SBatch b23 = {};
    b23.jobs[0] = { bu,  Wg3, nullptr, bs, bs, 0, 0 };
    b23.jobs[1] = { bv,  Wg3, nullptr, bt, bt, 0, 0 };
    b23.jobs[2] = { bx1, Wg1, nullptr, nullptr, bp,  0, 0 }; // p1
    b23.jobs[3] = { bx1, Wg2, nullptr, nullptr, bq,  0, 0 }; // q1
    b23.jobs[4] = { bx1, Wgo, bgo,     nullptr, bx2, 1, 0 }; // x2
    sgemm_batch_kernel<<<dim3(8,4,5), 256>>>(b23);

    // rel1 = f16(tanh(s_i + t_j + c)) -> plane A
    init_rel_kernel<<<dim3(XROWS, 4), 256>>>(bs, bt, bc, AH);

    // rel2 = tanh(rel1@Wg3 + p1_i + q1_j + b_gr) -> plane B
    hgemm_kernel<0><<<bgrid, 256, HG_SMEM>>>(AH, WgH, bp, bq, bgr, BH);

    // batch4: layer-2 row/col terms and x3 (x3 goes straight to d_out)
    SBatch b4 = {};
    b4.jobs[0] = { bx2, Wg1, nullptr, nullptr, bp,  0, 0 };  // p2
    b4.jobs[1] = { bx2, Wg2, nullptr, nullptr, bq,  0, 0 };  // q2
    b4.jobs[2] = { bx2, Wgo, bgo,     nullptr, out, 1, 0 };  // x3 -> out[0 : B*N*D]
    sgemm_batch_kernel<<<dim3(8,4,3), 256>>>(b4);

    // rel3 = tanh(rel2@Wg3 + p2_i + q2_j + b_gr) -> plane A
    hgemm_kernel<0><<<bgrid, 256, HG_SMEM>>>(BH, WgH, bp, bq, bgr, AH);

    // rel4 = rel3@W_esa + b_esa -> fp16 plane B
    hgemm_kernel<1><<<bgrid, 256, HG_SMEM>>>(AH, WeH, nullptr, nullptr, besa, BH);

    // softmax over i, then weighted sum over j (fp16 rel input)
    softmax_stats_kernel<<<XROWS, DD>>>(BH, bmx, binv);
    softmax_out_kernel<<<XROWS, DD>>>(BH, bmx, binv, out + XROWS*DD);
}

// round 12
// speedup vs baseline: 1.0789x; 1.0129x over previous
#include <cuda_runtime.h>
#include <cuda_fp16.h>
#include <math.h>
#include <stdint.h>

#define DD 512
#define NN 128
#define BB 2
#define MBIG (BB*NN*NN)     // 32768 rows for big GEMMs
#define XROWS (BB*NN)       // 256 rows for small GEMMs

// ---------------- scratch (static device allocations; no cudaMalloc) ----------------
__device__ __half g_AH[MBIG*DD];            // rel plane A (fp16)
__device__ __half g_BH[MBIG*DD];            // rel plane B (fp16)
__device__ __half g_WgH[DD*DD];             // Wg3^T  fp16 [n][k]
__device__ __half g_WeH[DD*DD];             // Wesa^T fp16 [n][k]
__device__ float g_u [XROWS*DD];
__device__ float g_v [XROWS*DD];
__device__ float g_s [XROWS*DD];
__device__ float g_t [XROWS*DD];
__device__ float g_p [XROWS*DD];
__device__ float g_q [XROWS*DD];
__device__ float g_x1[XROWS*DD];
__device__ float g_x2[XROWS*DD];
__device__ float g_c [DD];
__device__ float g_mx [XROWS*DD];
__device__ float g_inv[XROWS*DD];

// ---------------- helpers ----------------
__device__ __forceinline__ uint32_t smem_u32(const void* p) {
    uint32_t a;
    asm("{ .reg .u64 t; cvta.to.shared.u64 t, %1; cvt.u32.u64 %0, t; }" : "=r"(a) : "l"(p));
    return a;
}
__device__ __forceinline__ void mma16816(float* c, const uint32_t* a, const uint32_t* b) {
    asm volatile(
        "mma.sync.aligned.m16n8k16.row.col.f32.f16.f16.f32 "
        "{%0,%1,%2,%3},{%4,%5,%6,%7},{%8,%9},{%0,%1,%2,%3};"
        : "+f"(c[0]), "+f"(c[1]), "+f"(c[2]), "+f"(c[3])
        : "r"(a[0]), "r"(a[1]), "r"(a[2]), "r"(a[3]), "r"(b[0]), "r"(b[1]));
}
#define LDSM4(r0,r1,r2,r3,addr) \
    asm volatile("ldmatrix.sync.aligned.m8n8.x4.shared.b16 {%0,%1,%2,%3}, [%4];" \
        : "=r"(r0),"=r"(r1),"=r"(r2),"=r"(r3) : "r"(addr))
__device__ __forceinline__ void cp16(uint32_t dst, const void* src) {
    asm volatile("cp.async.cg.shared.global [%0], [%1], 16;" :: "r"(dst), "l"(src) : "memory");
}
// packed f32x2 helpers (exact IEEE fp32 per lane)
__device__ __forceinline__ unsigned long long pack2s(float v) {
    unsigned long long r;
    asm("mov.b64 %0, {%1, %1};" : "=l"(r) : "f"(v));
    return r;
}
__device__ __forceinline__ void ffma2(unsigned long long& acc,
                                      unsigned long long a, unsigned long long b) {
    asm("fma.rn.f32x2 %0, %1, %2, %0;" : "+l"(acc) : "l"(a), "l"(b));
}
__device__ __forceinline__ float2 unpack2(unsigned long long v) {
    float2 r;
    asm("mov.b64 {%0, %1}, %2;" : "=f"(r.x), "=f"(r.y) : "l"(v));
    return r;
}
// fast tanh: abs err ~1e-7, saturates correctly at +/-inf
__device__ __forceinline__ float ftanh(float x) {
    float e = __expf(2.0f * x);
    return 1.0f - __fdividef(2.0f, e + 1.0f);
}

// ---------------- weight transpose+f16 (both weights in one launch) ----------------
__global__ void transsplit_kernel(const float* __restrict__ W0, __half* __restrict__ Wh0,
                                  const float* __restrict__ W1, __half* __restrict__ Wh1) {
    const float* W  = blockIdx.z ? W1  : W0;
    __half*      Wh = blockIdx.z ? Wh1 : Wh0;
    __shared__ float tile[32][33];
    int x = blockIdx.x * 32 + threadIdx.x;
    int y = blockIdx.y * 32 + threadIdx.y;
    #pragma unroll
    for (int r = 0; r < 32; r += 8) tile[threadIdx.y + r][threadIdx.x] = W[(y + r) * DD + x];
    __syncthreads();
    x = blockIdx.y * 32 + threadIdx.x;   // now k index
    y = blockIdx.x * 32 + threadIdx.y;   // now n index
    #pragma unroll
    for (int r = 0; r < 32; r += 8)
        Wh[(y + r) * DD + x] = __float2half_rn(tile[threadIdx.x][threadIdx.y + r]);
}

// ---------------- c = b_rel @ Wg3 + b_gr ----------------
__global__ void cvec_kernel(const float* __restrict__ b_rel,
                            const float* __restrict__ Wg3,
                            const float* __restrict__ b_gr,
                            float* __restrict__ c) {
    int d = threadIdx.x;
    float acc = b_gr[d];
    #pragma unroll 8
    for (int k = 0; k < DD; ++k)
        acc += b_rel[k] * Wg3[k*DD + d];
    c[d] = acc;
}

// ---------------- batched small GEMM (FFMA2 + double buffer): C = act(A@W [+bias] [+Cadd]) ----------------
struct SJob {
    const float* A; const float* W; const float* bias; const float* Cadd;
    float* C; int act; int pad;
};
struct SBatch { SJob jobs[5]; };

__global__ __launch_bounds__(256)
void sgemm_batch_kernel(SBatch batch) {
    SJob jb = batch.jobs[blockIdx.z];
    __shared__ float As[2][32][68];
    __shared__ float Bs[2][32][64];
    int t  = threadIdx.x;
    int tx = t & 15, ty = t >> 4;
    int n0 = blockIdx.x << 6, m0 = blockIdx.y << 6;
    int arow = t >> 2, aseg = (t & 3) << 3;   // 64 m-rows, 8 k-floats each
    int bk = t >> 3, bn = (t & 7) << 3;       // 32 k-rows, 8 n-floats each
    const float* Aptr = jb.A + (m0 + arow) * DD + aseg;
    const float* Bptr = jb.W + bk * DD + n0 + bn;

    // preload chunk 0 into registers, store to buffer 0
    float4 av0 = *(const float4*)(Aptr);
    float4 av1 = *(const float4*)(Aptr + 4);
    float4 bv0 = *(const float4*)(Bptr);
    float4 bv1 = *(const float4*)(Bptr + 4);
    As[0][aseg+0][arow]=av0.x; As[0][aseg+1][arow]=av0.y;
    As[0][aseg+2][arow]=av0.z; As[0][aseg+3][arow]=av0.w;
    As[0][aseg+4][arow]=av1.x; As[0][aseg+5][arow]=av1.y;
    As[0][aseg+6][arow]=av1.z; As[0][aseg+7][arow]=av1.w;
    *(float4*)&Bs[0][bk][bn]   = bv0;
    *(float4*)&Bs[0][bk][bn+4] = bv1;
    __syncthreads();

    unsigned long long acc2[4][2] = {};
    for (int kt = 0; kt < DD/32; ++kt) {
        int buf = kt & 1;
        if (kt < DD/32 - 1) {     // issue loads for kt+1 (latency hidden by compute)
            av0 = *(const float4*)(Aptr + (kt+1)*32);
            av1 = *(const float4*)(Aptr + (kt+1)*32 + 4);
            bv0 = *(const float4*)(Bptr + (kt+1)*32*DD);
            bv1 = *(const float4*)(Bptr + (kt+1)*32*DD + 4);
        }
        #pragma unroll
        for (int kk = 0; kk < 32; ++kk) {
            float4 a = *(const float4*)&As[buf][kk][ty<<2];
            ulonglong2 b2 = *(const ulonglong2*)&Bs[buf][kk][tx<<2];
            unsigned long long a0 = pack2s(a.x), a1 = pack2s(a.y);
            unsigned long long a2 = pack2s(a.z), a3 = pack2s(a.w);
            ffma2(acc2[0][0], a0, b2.x); ffma2(acc2[0][1], a0, b2.y);
            ffma2(acc2[1][0], a1, b2.x); ffma2(acc2[1][1], a1, b2.y);
            ffma2(acc2[2][0], a2, b2.x); ffma2(acc2[2][1], a2, b2.y);
            ffma2(acc2[3][0], a3, b2.x); ffma2(acc2[3][1], a3, b2.y);
        }
        if (kt < DD/32 - 1) {     // store kt+1 into the idle buffer, then one sync
            int nb = buf ^ 1;
            As[nb][aseg+0][arow]=av0.x; As[nb][aseg+1][arow]=av0.y;
            As[nb][aseg+2][arow]=av0.z; As[nb][aseg+3][arow]=av0.w;
            As[nb][aseg+4][arow]=av1.x; As[nb][aseg+5][arow]=av1.y;
            As[nb][aseg+6][arow]=av1.z; As[nb][aseg+7][arow]=av1.w;
            *(float4*)&Bs[nb][bk][bn]   = bv0;
            *(float4*)&Bs[nb][bk][bn+4] = bv1;
            __syncthreads();
        }
    }

    int n = n0 + (tx<<2);
    float4 bb = make_float4(0.f, 0.f, 0.f, 0.f);
    if (jb.bias) bb = *(const float4*)(jb.bias + n);
    #pragma unroll
    for (int mm = 0; mm < 4; ++mm) {
        int m = m0 + (ty<<2) + mm;
        float2 lo = unpack2(acc2[mm][0]);
        float2 hi = unpack2(acc2[mm][1]);
        float4 r = make_float4(lo.x+bb.x, lo.y+bb.y, hi.x+bb.z, hi.y+bb.w);
        if (jb.Cadd) {
            float4 cv = *(const float4*)(jb.Cadd + m*DD + n);
            r.x += cv.x; r.y += cv.y; r.z += cv.z; r.w += cv.w;
        }
        if (jb.act) { r.x=ftanh(r.x); r.y=ftanh(r.y); r.z=ftanh(r.z); r.w=ftanh(r.w); }
        *(float4*)&jb.C[m*DD + n] = r;
    }
}

// ---------------- rel1 init: f16(tanh(s_i + t_j + c)) ----------------
__global__ __launch_bounds__(256)
void init_rel_kernel(const float* __restrict__ s, const float* __restrict__ t,
                     const float* __restrict__ c, __half* __restrict__ RH) {
    __shared__ float srow[DD];
    int bi = blockIdx.x;                 // b*128 + i
    int b  = bi >> 7;
    int tid = threadIdx.x;
    #pragma unroll
    for (int d = tid; d < DD; d += 256) srow[d] = s[bi * DD + d] + c[d];
    __syncthreads();
    int j0 = blockIdx.y * 32;
    int d = tid * 2;
    for (int j = j0; j < j0 + 32; ++j) {
        const float* trow = t + (size_t)((b << 7) + j) * DD;
        float v0 = ftanh(srow[d]   + trow[d]);
        float v1 = ftanh(srow[d+1] + trow[d+1]);
        size_t m = (size_t)bi * NN + j;
        *(__half2*)&RH[m * DD + d] = __halves2half2(__float2half_rn(v0), __float2half_rn(v1));
    }
}

// ================= big GEMM via mma.sync (fp16, 3-stage cp.async ring) =================
// C[32768,512] = A @ Wt^T. Per-CTA tile 128x128, K chunks of 32, 3 smem stages.
// Stage layout (row stride 80B = 64 data + 16 pad): A +0, B +10240; stage 20480 B.
// MODE 0: v = tanh(D + P[b,i,:] + Q[b,j,:] + bias) -> Chi (fp16)
// MODE 1: v = D + bias -> Chi (fp16)
#define HG_SMEM (3*20480)

template<int MODE>
__global__ __launch_bounds__(256, 2)
void hgemm_kernel(const __half* __restrict__ Ah, const __half* __restrict__ Bh,
                  const float* __restrict__ P, const float* __restrict__ Q,
                  const float* __restrict__ bias, __half* __restrict__ Chi) {
    extern __shared__ __align__(16) char sm[];
    const uint32_t smBase = smem_u32(sm);
    const int tid = threadIdx.x;
    const int n0 = blockIdx.x << 7, m0 = blockIdx.y << 7;

    // --- cp.async: 2 groups of 128 threads; each thread one row (64 B = 4 x 16B) ---
    const int mat = tid >> 7, tt = tid & 127;
    const __half* plane = mat ? (Bh + (size_t)(n0 + tt) * DD) : (Ah + (size_t)(m0 + tt) * DD);
    const uint32_t dstoff = (uint32_t)mat * 10240u + (uint32_t)tt * 80u;

    const int lane = tid & 31, wid = tid >> 5;
    const int g = lane >> 2, q = lane & 3;
    const int wm = (wid & 1) * 64, wn = (wid >> 1) * 32;

    // ldmatrix lane addressing
    const int lr = lane & 7, sub = lane >> 3;
    const uint32_t rowsel = (uint32_t)((sub & 1) * 8 + lr);
    const uint32_t colsel = (uint32_t)((sub >> 1) * 16);
    const uint32_t aoff = (uint32_t)(wm + rowsel) * 80u + colsel;            // + mt*1280 + ks*32
    const uint32_t boff = 10240u + (uint32_t)(wn + rowsel) * 80u + colsel;   // + ntp*1280 + ks*32

    const uint32_t stage0 = smBase, stage1 = smBase + 20480u, stage2 = smBase + 40960u;

    float cacc[4][4][4];
    #pragma unroll
    for (int a = 0; a < 4; ++a)
        #pragma unroll
        for (int b = 0; b < 4; ++b)
            #pragma unroll
            for (int e = 0; e < 4; ++e) cacc[a][b][e] = 0.f;

    // prologue: chunks 0 -> stage0, 1 -> stage1
    {
        uint32_t d = stage0 + dstoff;
        #pragma unroll
        for (int sg = 0; sg < 4; ++sg) cp16(d + sg*16, plane + sg*8);
        asm volatile("cp.async.commit_group;" ::: "memory");
        d = stage1 + dstoff;
        const __half* sp = plane + 32;
        #pragma unroll
        for (int sg = 0; sg < 4; ++sg) cp16(d + sg*16, sp + sg*8);
        asm volatile("cp.async.commit_group;" ::: "memory");
    }

    uint32_t stComp = stage0, stLoad = stage2;   // compute stage for kc, load target for kc+2
    for (int kc = 0; kc < 16; ++kc) {
        if (kc < 15) asm volatile("cp.async.wait_group 1;" ::: "memory");
        else         asm volatile("cp.async.wait_group 0;" ::: "memory");
        __syncthreads();   // chunk kc visible to all; all warps done computing chunk kc-1

        if (kc + 2 < 16) {
            uint32_t d = stLoad + dstoff;
            const __half* sp = plane + (kc + 2) * 32;
            #pragma unroll
            for (int sg = 0; sg < 4; ++sg) cp16(d + sg*16, sp + sg*8);
            asm volatile("cp.async.commit_group;" ::: "memory");
        }

        uint32_t bufb = stComp;
        #pragma unroll
        for (int ks = 0; ks < 2; ++ks) {
            uint32_t kso = (uint32_t)(ks * 32);
            uint32_t bfh[4][2];
            #pragma unroll
            for (int ntp = 0; ntp < 2; ++ntp) {
                uint32_t ba = bufb + boff + (uint32_t)ntp * 1280u + kso;
                uint32_t r0, r1, r2, r3;
                LDSM4(r0, r1, r2, r3, ba);
                bfh[2*ntp][0]=r0; bfh[2*ntp+1][0]=r1; bfh[2*ntp][1]=r2; bfh[2*ntp+1][1]=r3;
            }
            #pragma unroll
            for (int mt = 0; mt < 4; ++mt) {
                uint32_t aa = bufb + aoff + (uint32_t)mt * 1280u + kso;
                uint32_t ah[4];
                LDSM4(ah[0], ah[1], ah[2], ah[3], aa);
                #pragma unroll
                for (int nt = 0; nt < 4; ++nt)
                    mma16816(cacc[mt][nt], ah, bfh[nt]);
            }
        }
        // rotate stages
        uint32_t newComp = (stComp == stage2) ? stage0 : stComp + 20480u;
        stLoad = stComp;
        stComp = newComp;
    }

    // ---- epilogue ----
    #pragma unroll
    for (int mt = 0; mt < 4; ++mt) {
        #pragma unroll
        for (int nt = 0; nt < 4; ++nt) {
            int col = n0 + wn + nt*8 + q*2;
            float b0 = bias[col], b1 = bias[col + 1];
            #pragma unroll
            for (int rh = 0; rh < 2; ++rh) {
                int r = m0 + wm + mt*16 + g + rh*8;
                float v0 = cacc[mt][nt][rh*2 + 0] + b0;
                float v1 = cacc[mt][nt][rh*2 + 1] + b1;
                if (MODE == 0) {
                    int b = r >> 14, ii = (r >> 7) & 127, jj = r & 127;
                    const float* pr = P + (size_t)(((b<<7)+ii)) * DD;
                    const float* qr = Q + (size_t)(((b<<7)+jj)) * DD;
                    v0 = ftanh(v0 + pr[col]   + qr[col]);
                    v1 = ftanh(v1 + pr[col+1] + qr[col+1]);
                }
                *(__half2*)&Chi[(size_t)r * DD + col] =
                    __halves2half2(__float2half_rn(v0), __float2half_rn(v1));
            }
        }
    }
}

// ---------------- softmax pass A: per (b,j,d) max & 1/sumexp over i (fp16 rel) ----------------
__global__ void softmax_stats_kernel(const __half* __restrict__ rel,
                                     float* __restrict__ mx, float* __restrict__ inv) {
    int bj = blockIdx.x;            // b*NN + j
    int b = bj >> 7, j = bj & 127;
    int d = threadIdx.x;
    const __half* ptr = rel + (size_t)((b << 14) + j) * DD + d;
    float m = -1e30f;
    #pragma unroll 8
    for (int i = 0; i < NN; ++i) m = fmaxf(m, __half2float(ptr[(size_t)i * NN * DD]));
    float s = 0.f;
    #pragma unroll 8
    for (int i = 0; i < NN; ++i) s += __expf(__half2float(ptr[(size_t)i * NN * DD]) - m);
    int o = bj * DD + d;
    mx[o] = m;
    inv[o] = 1.0f / s;
}

// ---------------- softmax pass B: out[b,i,d] = sum_j softmax_i(rel)[b,i,j,d]*rel ----------------
__global__ void softmax_out_kernel(const __half* __restrict__ rel,
                                   const float* __restrict__ mx,
                                   const float* __restrict__ inv,
                                   float* __restrict__ out) {
    int bi = blockIdx.x;            // b*NN + i
    int b = bi >> 7;
    int d = threadIdx.x;
    const __half* ptr = rel + (size_t)bi * NN * DD + d;
    const float* mxp = mx  + (b << 7) * DD + d;
    const float* ivp = inv + (b << 7) * DD + d;
    float acc = 0.f;
    #pragma unroll 8
    for (int j = 0; j < NN; ++j) {
        float v = __half2float(ptr[(size_t)j * DD]);
        acc += v * __expf(v - mxp[j * DD]) * ivp[j * DD];
    }
    out[bi * DD + d] = acc;
}

// ---------------- host ----------------
extern "C" void kernel_launch(void* const* d_in, const int* in_sizes, int n_in,
                              void* d_out, int out_size) {
    const float* x0   = (const float*)d_in[0];
    const float* Wrel = (const float*)d_in[1];
    const float* brel = (const float*)d_in[2];
    const float* Wgo  = (const float*)d_in[3];
    const float* bgo  = (const float*)d_in[4];
    const float* Wgr  = (const float*)d_in[5];
    const float* bgr  = (const float*)d_in[6];
    const float* Wesa = (const float*)d_in[7];
    const float* besa = (const float*)d_in[8];
    float* out = (float*)d_out;

    const float* Wra = Wrel;                 // W_rel[0:D]
    const float* Wrb = Wrel + DD*DD;         // W_rel[D:2D]
    const float* Wg1 = Wgr;                  // W_gr[0:D]
    const float* Wg2 = Wgr + DD*DD;          // W_gr[D:2D]
    const float* Wg3 = Wgr + 2*DD*DD;        // W_gr[2D:3D]

    float *bu, *bv, *bs, *bt, *bp, *bq, *bx1, *bx2, *bc, *bmx, *binv;
    __half *AH, *BH, *WgH, *WeH;
    cudaGetSymbolAddress((void**)&AH, g_AH);
    cudaGetSymbolAddress((void**)&BH, g_BH);
    cudaGetSymbolAddress((void**)&WgH, g_WgH);
    cudaGetSymbolAddress((void**)&WeH, g_WeH);
    cudaGetSymbolAddress((void**)&bu,  g_u);
    cudaGetSymbolAddress((void**)&bv,  g_v);
    cudaGetSymbolAddress((void**)&bs,  g_s);
    cudaGetSymbolAddress((void**)&bt,  g_t);
    cudaGetSymbolAddress((void**)&bp,  g_p);
    cudaGetSymbolAddress((void**)&bq,  g_q);
    cudaGetSymbolAddress((void**)&bx1, g_x1);
    cudaGetSymbolAddress((void**)&bx2, g_x2);
    cudaGetSymbolAddress((void**)&bc,  g_c);
    cudaGetSymbolAddress((void**)&bmx, g_mx);
    cudaGetSymbolAddress((void**)&binv, g_inv);

    cudaFuncSetAttribute(hgemm_kernel<0>, cudaFuncAttributeMaxDynamicSharedMemorySize, HG_SMEM);
    cudaFuncSetAttribute(hgemm_kernel<1>, cudaFuncAttributeMaxDynamicSharedMemorySize, HG_SMEM);

    dim3 bgrid(4, 256);   // 512/128 n-tiles x 32768/128 m-tiles
    dim3 tgrid(16, 16, 2), tblk(32, 8);

    // both weight transposes in one launch
    transsplit_kernel<<<tgrid, tblk>>>(Wg3, WgH, Wesa, WeH);

    // c = b_rel @ Wg3 + b_gr
    cvec_kernel<<<1, DD>>>(brel, Wg3, bgr, bc);

    // batch1: everything that depends only on x0
    SBatch b1 = {};
    b1.jobs[0] = { x0, Wra, nullptr, nullptr, bu,  0, 0 };   // u = x0@Wra
    b1.jobs[1] = { x0, Wrb, nullptr, nullptr, bv,  0, 0 };   // v = x0@Wrb
    b1.jobs[2] = { x0, Wg1, nullptr, nullptr, bs,  0, 0 };   // s0 = x0@Wg1
    b1.jobs[3] = { x0, Wg2, nullptr, nullptr, bt,  0, 0 };   // t0 = x0@Wg2
    b1.jobs[4] = { x0, Wgo, bgo,     nullptr, bx1, 1, 0 };   // x1 = tanh(x0@Wgo+bgo)
    sgemm_batch_kernel<<<dim3(8,4,5), 256>>>(b1);

    // batch23 merged: s += u@Wg3 ; t += v@Wg3 ; p1 ; q1 ; x2
    SBatch b23 = {};
    b23.jobs[0] = { bu,  Wg3, nullptr, bs, bs, 0, 0 };
    b23.jobs[1] = { bv,  Wg3, nullptr, bt, bt, 0, 0 };
    b23.jobs[2] = { bx1, Wg1, nullptr, nullptr, bp,  0, 0 }; // p1
    b23.jobs[3] = { bx1, Wg2, nullptr, nullptr, bq,  0, 0 }; // q1
    b23.jobs[4] = { bx1, Wgo, bgo,     nullptr, bx2, 1, 0 }; // x2
    sgemm_batch_kernel<<<dim3(8,4,5), 256>>>(b23);

    // rel1 = f16(tanh(s_i + t_j + c)) -> plane A
    init_rel_kernel<<<dim3(XROWS, 4), 256>>>(bs, bt, bc, AH);

    // rel2 = tanh(rel1@Wg3 + p1_i + q1_j + b_gr) -> plane B
    hgemm_kernel<0><<<bgrid, 256, HG_SMEM>>>(AH, WgH, bp, bq, bgr, BH);

    // batch4: layer-2 row/col terms and x3 (x3 goes straight to d_out)
    SBatch b4 = {};
    b4.jobs[0] = { bx2, Wg1, nullptr, nullptr, bp,  0, 0 };  // p2
    b4.jobs[1] = { bx2, Wg2, nullptr, nullptr, bq,  0, 0 };  // q2
    b4.jobs[2] = { bx2, Wgo, bgo,     nullptr, out, 1, 0 };  // x3 -> out[0 : B*N*D]
    sgemm_batch_kernel<<<dim3(8,4,3), 256>>>(b4);

    // rel3 = tanh(rel2@Wg3 + p2_i + q2_j + b_gr) -> plane A
    hgemm_kernel<0><<<bgrid, 256, HG_SMEM>>>(BH, WgH, bp, bq, bgr, AH);

    // rel4 = rel3@W_esa + b_esa -> fp16 plane B
    hgemm_kernel<1><<<bgrid, 256, HG_SMEM>>>(AH, WeH, nullptr, nullptr, besa, BH);

    // softmax over i, then weighted sum over j (fp16 rel input)
    softmax_stats_kernel<<<XROWS, DD>>>(BH, bmx, binv);
    softmax_out_kernel<<<XROWS, DD>>>(BH, bmx, binv, out + XROWS*DD);
}

// round 13
// speedup vs baseline: 1.1209x; 1.0390x over previous
#include <cuda_runtime.h>
#include <cuda_fp16.h>
#include <math.h>
#include <stdint.h>

#define DD 512
#define NN 128
#define BB 2
#define MBIG (BB*NN*NN)     // 32768 rows for big GEMMs
#define XROWS (BB*NN)       // 256 rows for small GEMMs

// ---------------- scratch (static device allocations; no cudaMalloc) ----------------
__device__ __half g_AH[MBIG*DD];            // rel plane A (fp16)
__device__ __half g_BH[MBIG*DD];            // rel plane B (fp16)
__device__ __half g_WgH[DD*DD];             // Wg3^T  fp16 [n][k]
__device__ __half g_WeH[DD*DD];             // Wesa^T fp16 [n][k]
__device__ __half g_WraT[DD*DD], g_WrbT[DD*DD];
__device__ __half g_Wg1T[DD*DD], g_Wg2T[DD*DD], g_WgoT[DD*DD];
__device__ __half g_X0H[XROWS*DD];
__device__ __half g_UH [XROWS*DD];
__device__ __half g_VH [XROWS*DD];
__device__ __half g_X1H[XROWS*DD];
__device__ __half g_X2H[XROWS*DD];
__device__ float g_s [XROWS*DD];
__device__ float g_t [XROWS*DD];
__device__ float g_p [XROWS*DD];
__device__ float g_q [XROWS*DD];
__device__ float g_c [DD];
__device__ float g_mx [XROWS*DD];
__device__ float g_inv[XROWS*DD];

// ---------------- helpers ----------------
__device__ __forceinline__ uint32_t smem_u32(const void* p) {
    uint32_t a;
    asm("{ .reg .u64 t; cvta.to.shared.u64 t, %1; cvt.u32.u64 %0, t; }" : "=r"(a) : "l"(p));
    return a;
}
__device__ __forceinline__ void mma16816(float* c, const uint32_t* a, const uint32_t* b) {
    asm volatile(
        "mma.sync.aligned.m16n8k16.row.col.f32.f16.f16.f32 "
        "{%0,%1,%2,%3},{%4,%5,%6,%7},{%8,%9},{%0,%1,%2,%3};"
        : "+f"(c[0]), "+f"(c[1]), "+f"(c[2]), "+f"(c[3])
        : "r"(a[0]), "r"(a[1]), "r"(a[2]), "r"(a[3]), "r"(b[0]), "r"(b[1]));
}
#define LDSM4(r0,r1,r2,r3,addr) \
    asm volatile("ldmatrix.sync.aligned.m8n8.x4.shared.b16 {%0,%1,%2,%3}, [%4];" \
        : "=r"(r0),"=r"(r1),"=r"(r2),"=r"(r3) : "r"(addr))
__device__ __forceinline__ void cp16(uint32_t dst, const void* src) {
    asm volatile("cp.async.cg.shared.global [%0], [%1], 16;" :: "r"(dst), "l"(src) : "memory");
}
// fast tanh: abs err ~1e-7, saturates correctly at +/-inf
__device__ __forceinline__ float ftanh(float x) {
    float e = __expf(2.0f * x);
    return 1.0f - __fdividef(2.0f, e + 1.0f);
}

// ---------------- weight transpose+f16: 7 weights in one launch ----------------
struct TransBatch { const float* src[7]; __half* dst[7]; };
__global__ void transsplit_kernel(TransBatch tb) {
    const float* W  = tb.src[blockIdx.z];
    __half*      Wh = tb.dst[blockIdx.z];
    __shared__ float tile[32][33];
    int x = blockIdx.x * 32 + threadIdx.x;
    int y = blockIdx.y * 32 + threadIdx.y;
    #pragma unroll
    for (int r = 0; r < 32; r += 8) tile[threadIdx.y + r][threadIdx.x] = W[(y + r) * DD + x];
    __syncthreads();
    x = blockIdx.y * 32 + threadIdx.x;   // now k index
    y = blockIdx.x * 32 + threadIdx.y;   // now n index
    #pragma unroll
    for (int r = 0; r < 32; r += 8)
        Wh[(y + r) * DD + x] = __float2half_rn(tile[threadIdx.x][threadIdx.y + r]);
}

// ---------------- x0 -> fp16 ----------------
__global__ void tohalf_kernel(const float* __restrict__ src, __half* __restrict__ dst) {
    int i = (blockIdx.x * 256 + threadIdx.x) * 2;
    float2 v = *(const float2*)(src + i);
    *(__half2*)(dst + i) = __halves2half2(__float2half_rn(v.x), __float2half_rn(v.y));
}

// ---------------- c = b_rel @ Wg3 + b_gr ----------------
__global__ void cvec_kernel(const float* __restrict__ b_rel,
                            const float* __restrict__ Wg3,
                            const float* __restrict__ b_gr,
                            float* __restrict__ c) {
    int d = threadIdx.x;
    float acc = b_gr[d];
    #pragma unroll 8
    for (int k = 0; k < DD; ++k)
        acc += b_rel[k] * Wg3[k*DD + d];
    c[d] = acc;
}

// ---------------- rel1 init: f16(tanh(s_i + t_j + c)) ----------------
__global__ __launch_bounds__(256)
void init_rel_kernel(const float* __restrict__ s, const float* __restrict__ t,
                     const float* __restrict__ c, __half* __restrict__ RH) {
    __shared__ float srow[DD];
    int bi = blockIdx.x;                 // b*128 + i
    int b  = bi >> 7;
    int tid = threadIdx.x;
    #pragma unroll
    for (int d = tid; d < DD; d += 256) srow[d] = s[bi * DD + d] + c[d];
    __syncthreads();
    int j0 = blockIdx.y * 32;
    int d = tid * 2;
    for (int j = j0; j < j0 + 32; ++j) {
        const float* trow = t + (size_t)((b << 7) + j) * DD;
        float v0 = ftanh(srow[d]   + trow[d]);
        float v1 = ftanh(srow[d+1] + trow[d+1]);
        size_t m = (size_t)bi * NN + j;
        *(__half2*)&RH[m * DD + d] = __halves2half2(__float2half_rn(v0), __float2half_rn(v1));
    }
}

#define HG_SMEM (3*20480)

// ================= shared mainloop macro pieces live inline in both kernels =================

// ---------------- small batched tensor GEMM: C = act?(A@Wt [+bias] [+Cadd]) ----------------
// A fp16 [256,512], Wt fp16 [n][k]. Tile 128x128, grid (4, 2, njobs).
struct HJob {
    const __half* A; const __half* W; const float* bias; const float* Cadd;
    float* Cf; __half* Ch; int act; int pad;
};
struct HBatch { HJob jobs[5]; };

__global__ __launch_bounds__(256, 2)
void hsmall_kernel(HBatch batch) {
    HJob jb = batch.jobs[blockIdx.z];
    extern __shared__ __align__(16) char sm[];
    const uint32_t smBase = smem_u32(sm);
    const int tid = threadIdx.x;
    const int n0 = blockIdx.x << 7, m0 = blockIdx.y << 7;

    const int mat = tid >> 7, tt = tid & 127;
    const __half* plane = mat ? (jb.W + (size_t)(n0 + tt) * DD) : (jb.A + (size_t)(m0 + tt) * DD);
    const uint32_t dstoff = (uint32_t)mat * 10240u + (uint32_t)tt * 80u;

    const int lane = tid & 31, wid = tid >> 5;
    const int g = lane >> 2, q = lane & 3;
    const int wm = (wid & 1) * 64, wn = (wid >> 1) * 32;
    const int lr = lane & 7, sub = lane >> 3;
    const uint32_t rowsel = (uint32_t)((sub & 1) * 8 + lr);
    const uint32_t colsel = (uint32_t)((sub >> 1) * 16);
    const uint32_t aoff = (uint32_t)(wm + rowsel) * 80u + colsel;
    const uint32_t boff = 10240u + (uint32_t)(wn + rowsel) * 80u + colsel;

    const uint32_t stage0 = smBase, stage1 = smBase + 20480u, stage2 = smBase + 40960u;

    float cacc[4][4][4];
    #pragma unroll
    for (int a = 0; a < 4; ++a)
        #pragma unroll
        for (int b = 0; b < 4; ++b)
            #pragma unroll
            for (int e = 0; e < 4; ++e) cacc[a][b][e] = 0.f;

    {
        uint32_t d = stage0 + dstoff;
        #pragma unroll
        for (int sg = 0; sg < 4; ++sg) cp16(d + sg*16, plane + sg*8);
        asm volatile("cp.async.commit_group;" ::: "memory");
        d = stage1 + dstoff;
        const __half* sp = plane + 32;
        #pragma unroll
        for (int sg = 0; sg < 4; ++sg) cp16(d + sg*16, sp + sg*8);
        asm volatile("cp.async.commit_group;" ::: "memory");
    }

    uint32_t stComp = stage0, stLoad = stage2;
    for (int kc = 0; kc < 16; ++kc) {
        if (kc < 15) asm volatile("cp.async.wait_group 1;" ::: "memory");
        else         asm volatile("cp.async.wait_group 0;" ::: "memory");
        __syncthreads();
        if (kc + 2 < 16) {
            uint32_t d = stLoad + dstoff;
            const __half* sp = plane + (kc + 2) * 32;
            #pragma unroll
            for (int sg = 0; sg < 4; ++sg) cp16(d + sg*16, sp + sg*8);
            asm volatile("cp.async.commit_group;" ::: "memory");
        }
        uint32_t bufb = stComp;
        #pragma unroll
        for (int ks = 0; ks < 2; ++ks) {
            uint32_t kso = (uint32_t)(ks * 32);
            uint32_t bfh[4][2];
            #pragma unroll
            for (int ntp = 0; ntp < 2; ++ntp) {
                uint32_t ba = bufb + boff + (uint32_t)ntp * 1280u + kso;
                uint32_t r0, r1, r2, r3;
                LDSM4(r0, r1, r2, r3, ba);
                bfh[2*ntp][0]=r0; bfh[2*ntp+1][0]=r1; bfh[2*ntp][1]=r2; bfh[2*ntp+1][1]=r3;
            }
            #pragma unroll
            for (int mt = 0; mt < 4; ++mt) {
                uint32_t aa = bufb + aoff + (uint32_t)mt * 1280u + kso;
                uint32_t ah[4];
                LDSM4(ah[0], ah[1], ah[2], ah[3], aa);
                #pragma unroll
                for (int nt = 0; nt < 4; ++nt)
                    mma16816(cacc[mt][nt], ah, bfh[nt]);
            }
        }
        uint32_t newComp = (stComp == stage2) ? stage0 : stComp + 20480u;
        stLoad = stComp;
        stComp = newComp;
    }

    // ---- epilogue ----
    #pragma unroll
    for (int mt = 0; mt < 4; ++mt) {
        #pragma unroll
        for (int nt = 0; nt < 4; ++nt) {
            int col = n0 + wn + nt*8 + q*2;
            float b0 = 0.f, b1 = 0.f;
            if (jb.bias) { b0 = jb.bias[col]; b1 = jb.bias[col + 1]; }
            #pragma unroll
            for (int rh = 0; rh < 2; ++rh) {
                int r = m0 + wm + mt*16 + g + rh*8;
                float v0 = cacc[mt][nt][rh*2 + 0] + b0;
                float v1 = cacc[mt][nt][rh*2 + 1] + b1;
                if (jb.Cadd) {
                    float2 cv = *(const float2*)(jb.Cadd + (size_t)r * DD + col);
                    v0 += cv.x; v1 += cv.y;
                }
                if (jb.act) { v0 = ftanh(v0); v1 = ftanh(v1); }
                if (jb.Cf)
                    *(float2*)(jb.Cf + (size_t)r * DD + col) = make_float2(v0, v1);
                else
                    *(__half2*)(jb.Ch + (size_t)r * DD + col) =
                        __halves2half2(__float2half_rn(v0), __float2half_rn(v1));
            }
        }
    }
}

// ================= big GEMM via mma.sync (fp16, 3-stage cp.async ring) =================
template<int MODE>
__global__ __launch_bounds__(256, 2)
void hgemm_kernel(const __half* __restrict__ Ah, const __half* __restrict__ Bh,
                  const float* __restrict__ P, const float* __restrict__ Q,
                  const float* __restrict__ bias, __half* __restrict__ Chi) {
    extern __shared__ __align__(16) char sm[];
    const uint32_t smBase = smem_u32(sm);
    const int tid = threadIdx.x;
    const int n0 = blockIdx.x << 7, m0 = blockIdx.y << 7;

    const int mat = tid >> 7, tt = tid & 127;
    const __half* plane = mat ? (Bh + (size_t)(n0 + tt) * DD) : (Ah + (size_t)(m0 + tt) * DD);
    const uint32_t dstoff = (uint32_t)mat * 10240u + (uint32_t)tt * 80u;

    const int lane = tid & 31, wid = tid >> 5;
    const int g = lane >> 2, q = lane & 3;
    const int wm = (wid & 1) * 64, wn = (wid >> 1) * 32;
    const int lr = lane & 7, sub = lane >> 3;
    const uint32_t rowsel = (uint32_t)((sub & 1) * 8 + lr);
    const uint32_t colsel = (uint32_t)((sub >> 1) * 16);
    const uint32_t aoff = (uint32_t)(wm + rowsel) * 80u + colsel;
    const uint32_t boff = 10240u + (uint32_t)(wn + rowsel) * 80u + colsel;

    const uint32_t stage0 = smBase, stage1 = smBase + 20480u, stage2 = smBase + 40960u;

    float cacc[4][4][4];
    #pragma unroll
    for (int a = 0; a < 4; ++a)
        #pragma unroll
        for (int b = 0; b < 4; ++b)
            #pragma unroll
            for (int e = 0; e < 4; ++e) cacc[a][b][e] = 0.f;

    {
        uint32_t d = stage0 + dstoff;
        #pragma unroll
        for (int sg = 0; sg < 4; ++sg) cp16(d + sg*16, plane + sg*8);
        asm volatile("cp.async.commit_group;" ::: "memory");
        d = stage1 + dstoff;
        const __half* sp = plane + 32;
        #pragma unroll
        for (int sg = 0; sg < 4; ++sg) cp16(d + sg*16, sp + sg*8);
        asm volatile("cp.async.commit_group;" ::: "memory");
    }

    uint32_t stComp = stage0, stLoad = stage2;
    for (int kc = 0; kc < 16; ++kc) {
        if (kc < 15) asm volatile("cp.async.wait_group 1;" ::: "memory");
        else         asm volatile("cp.async.wait_group 0;" ::: "memory");
        __syncthreads();

        if (kc + 2 < 16) {
            uint32_t d = stLoad + dstoff;
            const __half* sp = plane + (kc + 2) * 32;
            #pragma unroll
            for (int sg = 0; sg < 4; ++sg) cp16(d + sg*16, sp + sg*8);
            asm volatile("cp.async.commit_group;" ::: "memory");
        }

        uint32_t bufb = stComp;
        #pragma unroll
        for (int ks = 0; ks < 2; ++ks) {
            uint32_t kso = (uint32_t)(ks * 32);
            uint32_t bfh[4][2];
            #pragma unroll
            for (int ntp = 0; ntp < 2; ++ntp) {
                uint32_t ba = bufb + boff + (uint32_t)ntp * 1280u + kso;
                uint32_t r0, r1, r2, r3;
                LDSM4(r0, r1, r2, r3, ba);
                bfh[2*ntp][0]=r0; bfh[2*ntp+1][0]=r1; bfh[2*ntp][1]=r2; bfh[2*ntp+1][1]=r3;
            }
            #pragma unroll
            for (int mt = 0; mt < 4; ++mt) {
                uint32_t aa = bufb + aoff + (uint32_t)mt * 1280u + kso;
                uint32_t ah[4];
                LDSM4(ah[0], ah[1], ah[2], ah[3], aa);
                #pragma unroll
                for (int nt = 0; nt < 4; ++nt)
                    mma16816(cacc[mt][nt], ah, bfh[nt]);
            }
        }
        uint32_t newComp = (stComp == stage2) ? stage0 : stComp + 20480u;
        stLoad = stComp;
        stComp = newComp;
    }

    // ---- epilogue ----
    #pragma unroll
    for (int mt = 0; mt < 4; ++mt) {
        #pragma unroll
        for (int nt = 0; nt < 4; ++nt) {
            int col = n0 + wn + nt*8 + q*2;
            float b0 = bias[col], b1 = bias[col + 1];
            #pragma unroll
            for (int rh = 0; rh < 2; ++rh) {
                int r = m0 + wm + mt*16 + g + rh*8;
                float v0 = cacc[mt][nt][rh*2 + 0] + b0;
                float v1 = cacc[mt][nt][rh*2 + 1] + b1;
                if (MODE == 0) {
                    int b = r >> 14, ii = (r >> 7) & 127, jj = r & 127;
                    const float* pr = P + (size_t)(((b<<7)+ii)) * DD;
                    const float* qr = Q + (size_t)(((b<<7)+jj)) * DD;
                    v0 = ftanh(v0 + pr[col]   + qr[col]);
                    v1 = ftanh(v1 + pr[col+1] + qr[col+1]);
                }
                *(__half2*)&Chi[(size_t)r * DD + col] =
                    __halves2half2(__float2half_rn(v0), __float2half_rn(v1));
            }
        }
    }
}

// ---------------- softmax pass A ----------------
__global__ void softmax_stats_kernel(const __half* __restrict__ rel,
                                     float* __restrict__ mx, float* __restrict__ inv) {
    int bj = blockIdx.x;            // b*NN + j
    int b = bj >> 7, j = bj & 127;
    int d = threadIdx.x;
    const __half* ptr = rel + (size_t)((b << 14) + j) * DD + d;
    float m = -1e30f;
    #pragma unroll 8
    for (int i = 0; i < NN; ++i) m = fmaxf(m, __half2float(ptr[(size_t)i * NN * DD]));
    float s = 0.f;
    #pragma unroll 8
    for (int i = 0; i < NN; ++i) s += __expf(__half2float(ptr[(size_t)i * NN * DD]) - m);
    int o = bj * DD + d;
    mx[o] = m;
    inv[o] = 1.0f / s;
}

// ---------------- softmax pass B ----------------
__global__ void softmax_out_kernel(const __half* __restrict__ rel,
                                   const float* __restrict__ mx,
                                   const float* __restrict__ inv,
                                   float* __restrict__ out) {
    int bi = blockIdx.x;            // b*NN + i
    int b = bi >> 7;
    int d = threadIdx.x;
    const __half* ptr = rel + (size_t)bi * NN * DD + d;
    const float* mxp = mx  + (b << 7) * DD + d;
    const float* ivp = inv + (b << 7) * DD + d;
    float acc = 0.f;
    #pragma unroll 8
    for (int j = 0; j < NN; ++j) {
        float v = __half2float(ptr[(size_t)j * DD]);
        acc += v * __expf(v - mxp[j * DD]) * ivp[j * DD];
    }
    out[bi * DD + d] = acc;
}

// ---------------- host ----------------
extern "C" void kernel_launch(void* const* d_in, const int* in_sizes, int n_in,
                              void* d_out, int out_size) {
    const float* x0   = (const float*)d_in[0];
    const float* Wrel = (const float*)d_in[1];
    const float* brel = (const float*)d_in[2];
    const float* Wgo  = (const float*)d_in[3];
    const float* bgo  = (const float*)d_in[4];
    const float* Wgr  = (const float*)d_in[5];
    const float* bgr  = (const float*)d_in[6];
    const float* Wesa = (const float*)d_in[7];
    const float* besa = (const float*)d_in[8];
    float* out = (float*)d_out;

    const float* Wra = Wrel;                 // W_rel[0:D]
    const float* Wrb = Wrel + DD*DD;         // W_rel[D:2D]
    const float* Wg1 = Wgr;                  // W_gr[0:D]
    const float* Wg2 = Wgr + DD*DD;          // W_gr[D:2D]
    const float* Wg3 = Wgr + 2*DD*DD;        // W_gr[2D:3D]

    float *bs, *bt, *bp, *bq, *bc, *bmx, *binv;
    __half *AH, *BH, *WgH, *WeH, *WraT, *WrbT, *Wg1T, *Wg2T, *WgoT;
    __half *X0H, *UH, *VH, *X1H, *X2H;
    cudaGetSymbolAddress((void**)&AH, g_AH);
    cudaGetSymbolAddress((void**)&BH, g_BH);
    cudaGetSymbolAddress((void**)&WgH, g_WgH);
    cudaGetSymbolAddress((void**)&WeH, g_WeH);
    cudaGetSymbolAddress((void**)&WraT, g_WraT);
    cudaGetSymbolAddress((void**)&WrbT, g_WrbT);
    cudaGetSymbolAddress((void**)&Wg1T, g_Wg1T);
    cudaGetSymbolAddress((void**)&Wg2T, g_Wg2T);
    cudaGetSymbolAddress((void**)&WgoT, g_WgoT);
    cudaGetSymbolAddress((void**)&X0H, g_X0H);
    cudaGetSymbolAddress((void**)&UH,  g_UH);
    cudaGetSymbolAddress((void**)&VH,  g_VH);
    cudaGetSymbolAddress((void**)&X1H, g_X1H);
    cudaGetSymbolAddress((void**)&X2H, g_X2H);
    cudaGetSymbolAddress((void**)&bs,  g_s);
    cudaGetSymbolAddress((void**)&bt,  g_t);
    cudaGetSymbolAddress((void**)&bp,  g_p);
    cudaGetSymbolAddress((void**)&bq,  g_q);
    cudaGetSymbolAddress((void**)&bc,  g_c);
    cudaGetSymbolAddress((void**)&bmx, g_mx);
    cudaGetSymbolAddress((void**)&binv, g_inv);

    cudaFuncSetAttribute(hgemm_kernel<0>, cudaFuncAttributeMaxDynamicSharedMemorySize, HG_SMEM);
    cudaFuncSetAttribute(hgemm_kernel<1>, cudaFuncAttributeMaxDynamicSharedMemorySize, HG_SMEM);
    cudaFuncSetAttribute(hsmall_kernel,  cudaFuncAttributeMaxDynamicSharedMemorySize, HG_SMEM);

    dim3 bgrid(4, 256);   // big GEMM grid

    // all 7 weight transposes in one launch
    TransBatch tb;
    tb.src[0]=Wg3;  tb.dst[0]=WgH;
    tb.src[1]=Wesa; tb.dst[1]=WeH;
    tb.src[2]=Wra;  tb.dst[2]=WraT;
    tb.src[3]=Wrb;  tb.dst[3]=WrbT;
    tb.src[4]=Wg1;  tb.dst[4]=Wg1T;
    tb.src[5]=Wg2;  tb.dst[5]=Wg2T;
    tb.src[6]=Wgo;  tb.dst[6]=WgoT;
    transsplit_kernel<<<dim3(16,16,7), dim3(32,8)>>>(tb);

    // x0 -> fp16 ; c = b_rel @ Wg3 + b_gr
    tohalf_kernel<<<XROWS*DD/512, 256>>>(x0, X0H);
    cvec_kernel<<<1, DD>>>(brel, Wg3, bgr, bc);

    // batch1 (A = x0h): u16, v16, s0(f32), t0(f32), x1(f16,tanh)
    HBatch hb1 = {};
    hb1.jobs[0] = { X0H, WraT, nullptr, nullptr, nullptr, UH,  0, 0 };
    hb1.jobs[1] = { X0H, WrbT, nullptr, nullptr, nullptr, VH,  0, 0 };
    hb1.jobs[2] = { X0H, Wg1T, nullptr, nullptr, bs,      nullptr, 0, 0 };
    hb1.jobs[3] = { X0H, Wg2T, nullptr, nullptr, bt,      nullptr, 0, 0 };
    hb1.jobs[4] = { X0H, WgoT, bgo,     nullptr, nullptr, X1H, 1, 0 };
    hsmall_kernel<<<dim3(4,2,5), 256, HG_SMEM>>>(hb1);

    // batch23: s += u@Wg3 ; t += v@Wg3 ; p1 ; q1 ; x2
    HBatch hb23 = {};
    hb23.jobs[0] = { UH,  WgH,  nullptr, bs, bs,      nullptr, 0, 0 };
    hb23.jobs[1] = { VH,  WgH,  nullptr, bt, bt,      nullptr, 0, 0 };
    hb23.jobs[2] = { X1H, Wg1T, nullptr, nullptr, bp, nullptr, 0, 0 };
    hb23.jobs[3] = { X1H, Wg2T, nullptr, nullptr, bq, nullptr, 0, 0 };
    hb23.jobs[4] = { X1H, WgoT, bgo,     nullptr, nullptr, X2H, 1, 0 };
    hsmall_kernel<<<dim3(4,2,5), 256, HG_SMEM>>>(hb23);

    // rel1 = f16(tanh(s_i + t_j + c)) -> plane A
    init_rel_kernel<<<dim3(XROWS, 4), 256>>>(bs, bt, bc, AH);

    // rel2 = tanh(rel1@Wg3 + p1_i + q1_j + b_gr) -> plane B
    hgemm_kernel<0><<<bgrid, 256, HG_SMEM>>>(AH, WgH, bp, bq, bgr, BH);

    // batch4: p2, q2 (f32), x3 (f32, tanh) -> out
    HBatch hb4 = {};
    hb4.jobs[0] = { X2H, Wg1T, nullptr, nullptr, bp,  nullptr, 0, 0 };
    hb4.jobs[1] = { X2H, Wg2T, nullptr, nullptr, bq,  nullptr, 0, 0 };
    hb4.jobs[2] = { X2H, WgoT, bgo,     nullptr, out, nullptr, 1, 0 };
    hsmall_kernel<<<dim3(4,2,3), 256, HG_SMEM>>>(hb4);

    // rel3 = tanh(rel2@Wg3 + p2_i + q2_j + b_gr) -> plane A
    hgemm_kernel<0><<<bgrid, 256, HG_SMEM>>>(BH, WgH, bp, bq, bgr, AH);

    // rel4 = rel3@W_esa + b_esa -> fp16 plane B
    hgemm_kernel<1><<<bgrid, 256, HG_SMEM>>>(AH, WeH, nullptr, nullptr, besa, BH);

    // softmax over i, then weighted sum over j (fp16 rel input)
    softmax_stats_kernel<<<XROWS, DD>>>(BH, bmx, binv);
    softmax_out_kernel<<<XROWS, DD>>>(BH, bmx, binv, out + XROWS*DD);
}